// round 11
// baseline (speedup 1.0000x reference)
#include <cuda_runtime.h>
#include <math.h>
#include <stdint.h>

#define B   32
#define LL  128
#define LR  128
#define D   512
#define A   128
#define OC  259   // 1+64 | 64 | 1+64 | 1+64

// ---- scratch (static device globals; no runtime allocation) ----
__device__ float g_algt[(B*LL + B*LR) * A];
__device__ float g_att[B*LL*D];
__device__ float g_probs[B*LL*LR];
__device__ float g_invnrt[B*LR];
__device__ int   g_idx[B*LL];
// pre-split bf16 hi/lo swizzled tiles: (b,chunk) tiles of 128 rows x 128B
__device__ __align__(16) unsigned char g_Lh[B*8*16384];
__device__ __align__(16) unsigned char g_Ll[B*8*16384];
__device__ __align__(16) unsigned char g_Rh[B*8*16384];
__device__ __align__(16) unsigned char g_Rl[B*8*16384];
// W1 transposed to B-operand tiles: 8 chunks x (128 a-rows x 64 d) hi/lo
__device__ __align__(16) unsigned char g_Wh[8*16384];
__device__ __align__(16) unsigned char g_Wl[8*16384];

__device__ __forceinline__ uint32_t swz(uint32_t x){ return x ^ ((x >> 3) & 0x70u); }
__device__ __forceinline__ uint32_t smem_u32(const void* p){
    uint32_t a;
    asm("{ .reg .u64 t; cvta.to.shared.u64 t, %1; cvt.u32.u64 %0, t; }" : "=r"(a) : "l"(p));
    return a;
}
__device__ __forceinline__ void split2(float x0, float x1, uint32_t& h, uint32_t& l){
    asm("cvt.rn.bf16x2.f32 %0, %1, %2;" : "=r"(h) : "f"(x1), "f"(x0));
    float h0 = __uint_as_float(h << 16), h1 = __uint_as_float(h & 0xffff0000u);
    asm("cvt.rn.bf16x2.f32 %0, %1, %2;" : "=r"(l) : "f"(x1 - h1), "f"(x0 - h0));
}

#define LDSM4(r0,r1,r2,r3,addr) \
    asm volatile("ldmatrix.sync.aligned.m8n8.x4.shared.b16 {%0,%1,%2,%3}, [%4];" \
        : "=r"(r0),"=r"(r1),"=r"(r2),"=r"(r3) : "r"(addr))
#define CP16(s,g) \
    asm volatile("cp.async.cg.shared.global [%0], [%1], 16;" :: "r"(s), "l"(g))
#define CPCOMMIT() asm volatile("cp.async.commit_group;")
#define CPWAIT1()  asm volatile("cp.async.wait_group 1;")
#define CPWAIT0()  asm volatile("cp.async.wait_group 0;")

__device__ __forceinline__ void mma_bf16(float* d, const uint32_t* a, const uint32_t* b){
    asm volatile("mma.sync.aligned.m16n8k16.row.col.f32.bf16.bf16.f32 "
        "{%0,%1,%2,%3}, {%4,%5,%6,%7}, {%8,%9}, {%0,%1,%2,%3};"
        : "+f"(d[0]),"+f"(d[1]),"+f"(d[2]),"+f"(d[3])
        : "r"(a[0]),"r"(a[1]),"r"(a[2]),"r"(a[3]), "r"(b[0]),"r"(b[1]));
}

// ============================================================================
// k_split: X (fp32) -> hi/lo bf16 swizzled tiles. grid (8, B). which: 0=L 1=R
// ============================================================================
__global__ void __launch_bounds__(256) k_split(const float* __restrict__ X, int which)
{
    int c = blockIdx.x, b = blockIdx.y, t = threadIdx.x;
    const float* Xb = X + ((size_t)b << 16) + c*64;
    size_t tile = ((size_t)(b*8 + c)) << 14;
    unsigned char* dh = (which ? g_Rh : g_Lh) + tile;
    unsigned char* dl = (which ? g_Rl : g_Ll) + tile;
    #pragma unroll
    for (int i = 0; i < 4; i++){
        int f = i*256 + t; int row = f >> 3, q = f & 7;
        const float* src = Xb + (size_t)row*512 + q*8;
        float4 v0 = *(const float4*)src, v1 = *(const float4*)(src + 4);
        uint32_t h01,l01,h23,l23,h45,l45,h67,l67;
        split2(v0.x, v0.y, h01, l01);
        split2(v0.z, v0.w, h23, l23);
        split2(v1.x, v1.y, h45, l45);
        split2(v1.z, v1.w, h67, l67);
        uint32_t off = swz((uint32_t)(row*128 + q*16));
        *(uint4*)(dh + off) = make_uint4(h01, h23, h45, h67);
        *(uint4*)(dl + off) = make_uint4(l01, l23, l45, l67);
    }
}

// ============================================================================
// k_splitW: W1 [d=512][a=128] -> transposed B tiles (rows=a, k=d). grid (8).
// ============================================================================
__global__ void __launch_bounds__(256) k_splitW(const float* __restrict__ W1)
{
    int c = blockIdx.x, t = threadIdx.x;
    size_t tile = ((size_t)c) << 14;
    #pragma unroll
    for (int i = 0; i < 8; i++){
        int f = i*256 + t; int row = f >> 4, q = f & 15;
        int d0 = c*64 + q*4;
        float w0 = W1[(size_t)(d0+0)*A + row];
        float w1 = W1[(size_t)(d0+1)*A + row];
        float w2 = W1[(size_t)(d0+2)*A + row];
        float w3 = W1[(size_t)(d0+3)*A + row];
        uint32_t h01,l01,h23,l23;
        split2(w0, w1, h01, l01);
        split2(w2, w3, h23, l23);
        uint32_t off = swz((uint32_t)(row*128 + q*8));
        *(uint2*)(g_Wh + tile + off) = make_uint2(h01, h23);
        *(uint2*)(g_Wl + tile + off) = make_uint2(l01, l23);
    }
}

// ============================================================================
// k_mpool_mma: CTA = (m, b).  C[l,r] = sum_d L[l,d]*(R[r,d]*K_m[d]).
// out[b,l,65+m] = tanh(max_r C).  dyn smem padded to 116736 B -> occ 1 by smem
// (launch_bounds(256,2) kept only as a 128-reg cap). Frees RF for side CTAs.
// ============================================================================
__global__ void __launch_bounds__(256, 2) k_mpool_mma(
    const float* __restrict__ Rr, const float* __restrict__ Kmp,
    float* __restrict__ out)
{
    extern __shared__ __align__(16) unsigned char dyn[];
    int m = blockIdx.x, b = blockIdx.y;
    int t = threadIdx.x, wid = t >> 5, lane = t & 31;
    uint32_t base = smem_u32(dyn);
    uint32_t Abuf[2] = {base, base + 32768};
    uint32_t Bh = base + 65536, Bl = base + 81920;
    float* sK = (float*)(dyn + 98304);
    for (int i = t; i < 512; i += 256) sK[i] = Kmp[(size_t)m*512 + i];

    {
        const unsigned char* gh = g_Lh + (((size_t)(b*8)) << 14);
        const unsigned char* gl = g_Ll + (((size_t)(b*8)) << 14);
        #pragma unroll
        for (int i = 0; i < 4; i++){
            uint32_t o = (uint32_t)(i*256 + t) * 16;
            CP16(Abuf[0] + o, gh + o);
            CP16(Abuf[0] + 16384 + o, gl + o);
        }
        CPCOMMIT();
    }
    __syncthreads();

    int wl = wid >> 2, wn = wid & 3;
    float acc[4][4][4];
    #pragma unroll
    for (int i = 0; i < 4; i++)
        #pragma unroll
        for (int j = 0; j < 4; j++)
            #pragma unroll
            for (int k = 0; k < 4; k++) acc[i][j][k] = 0.f;

    int rowA = lane & 15;
    int cbA  = lane >> 4;
    int rowB = ((lane >> 4) & 1) * 8 + (lane & 7);
    int cbB  = (lane >> 3) & 1;

    const float* Rb = Rr + ((size_t)b << 16);
    int rrow = t >> 3, rq = t & 7;

    for (int c = 0; c < 8; c++){
        if (c < 7){
            uint32_t nb = Abuf[(c+1) & 1];
            const unsigned char* gh = g_Lh + (((size_t)(b*8 + c+1)) << 14);
            const unsigned char* gl = g_Ll + (((size_t)(b*8 + c+1)) << 14);
            #pragma unroll
            for (int i = 0; i < 4; i++){
                uint32_t o = (uint32_t)(i*256 + t) * 16;
                CP16(nb + o, gh + o);
                CP16(nb + 16384 + o, gl + o);
            }
            CPCOMMIT();
        }
        {
            float4 k0 = *(const float4*)(sK + c*64 + rq*8);
            float4 k1 = *(const float4*)(sK + c*64 + rq*8 + 4);
            #pragma unroll
            for (int i = 0; i < 4; i++){
                int row = rrow + i*32;
                const float* src = Rb + (size_t)row*512 + c*64 + rq*8;
                float4 r0 = *(const float4*)src, r1 = *(const float4*)(src + 4);
                uint32_t h01,l01,h23,l23,h45,l45,h67,l67;
                split2(r0.x*k0.x, r0.y*k0.y, h01, l01);
                split2(r0.z*k0.z, r0.w*k0.w, h23, l23);
                split2(r1.x*k1.x, r1.y*k1.y, h45, l45);
                split2(r1.z*k1.z, r1.w*k1.w, h67, l67);
                uint32_t off = swz((uint32_t)(row*128 + rq*16));
                asm volatile("st.shared.v4.b32 [%0], {%1,%2,%3,%4};"
                             :: "r"(Bh+off), "r"(h01), "r"(h23), "r"(h45), "r"(h67));
                asm volatile("st.shared.v4.b32 [%0], {%1,%2,%3,%4};"
                             :: "r"(Bl+off), "r"(l01), "r"(l23), "r"(l45), "r"(l67));
            }
        }
        if (c < 7) { CPWAIT1(); } else { CPWAIT0(); }
        __syncthreads();

        uint32_t Ah = Abuf[c & 1], Al = Ah + 16384;
        #pragma unroll
        for (int ks = 0; ks < 4; ks++){
            uint32_t aoffs[4], boffs[2];
            #pragma unroll
            for (int mt = 0; mt < 4; mt++)
                aoffs[mt] = swz((uint32_t)((wl*64 + mt*16 + rowA)*128 + ks*32 + cbA*16));
            #pragma unroll
            for (int jp = 0; jp < 2; jp++)
                boffs[jp] = swz((uint32_t)((wn*32 + jp*16 + rowB)*128 + ks*32 + cbB*16));

            uint32_t bh_[4][2];
            #pragma unroll
            for (int jp = 0; jp < 2; jp++)
                LDSM4(bh_[jp*2][0], bh_[jp*2][1], bh_[jp*2+1][0], bh_[jp*2+1][1], Bh + boffs[jp]);
            {
                uint32_t al_[4][4];
                #pragma unroll
                for (int mt = 0; mt < 4; mt++)
                    LDSM4(al_[mt][0], al_[mt][1], al_[mt][2], al_[mt][3], Al + aoffs[mt]);
                #pragma unroll
                for (int mt = 0; mt < 4; mt++)
                    #pragma unroll
                    for (int nt = 0; nt < 4; nt++)
                        mma_bf16(acc[mt][nt], al_[mt], bh_[nt]);
            }
            uint32_t ah_[4][4];
            #pragma unroll
            for (int mt = 0; mt < 4; mt++)
                LDSM4(ah_[mt][0], ah_[mt][1], ah_[mt][2], ah_[mt][3], Ah + aoffs[mt]);
            #pragma unroll
            for (int mt = 0; mt < 4; mt++)
                #pragma unroll
                for (int nt = 0; nt < 4; nt++)
                    mma_bf16(acc[mt][nt], ah_[mt], bh_[nt]);
            {
                uint32_t bl_[4][2];
                #pragma unroll
                for (int jp = 0; jp < 2; jp++)
                    LDSM4(bl_[jp*2][0], bl_[jp*2][1], bl_[jp*2+1][0], bl_[jp*2+1][1], Bl + boffs[jp]);
                #pragma unroll
                for (int mt = 0; mt < 4; mt++)
                    #pragma unroll
                    for (int nt = 0; nt < 4; nt++)
                        mma_bf16(acc[mt][nt], ah_[mt], bl_[nt]);
            }
        }
        __syncthreads();
    }

    float* red = (float*)dyn;
    int g = lane >> 2, tg = lane & 3;
    #pragma unroll
    for (int mt = 0; mt < 4; mt++){
        float m0 = -1e30f, m1 = -1e30f;
        #pragma unroll
        for (int nt = 0; nt < 4; nt++){
            m0 = fmaxf(m0, fmaxf(acc[mt][nt][0], acc[mt][nt][1]));
            m1 = fmaxf(m1, fmaxf(acc[mt][nt][2], acc[mt][nt][3]));
        }
        m0 = fmaxf(m0, __shfl_xor_sync(0xffffffffu, m0, 1));
        m0 = fmaxf(m0, __shfl_xor_sync(0xffffffffu, m0, 2));
        m1 = fmaxf(m1, __shfl_xor_sync(0xffffffffu, m1, 1));
        m1 = fmaxf(m1, __shfl_xor_sync(0xffffffffu, m1, 2));
        if (tg == 0){
            red[(wl*64 + mt*16 + g)*4 + wn]     = m0;
            red[(wl*64 + mt*16 + g + 8)*4 + wn] = m1;
        }
    }
    __syncthreads();
    if (t < 128){
        float v = fmaxf(fmaxf(red[t*4], red[t*4+1]), fmaxf(red[t*4+2], red[t*4+3]));
        out[((size_t)(b*LL + t))*OC + 65 + m] = tanhf(v);
    }
}

// ============================================================================
// k_algt_mma: tanh([L;R] @ W1) (*diag for L rows), 3-term split bf16 MMA.
// grid 64, 256 thr.  SINGLE-buffered: dyn smem 65536 B (fits beside mpool).
// ============================================================================
__global__ void __launch_bounds__(256) k_algt_mma(const float* __restrict__ diag)
{
    extern __shared__ __align__(16) unsigned char dyn[];
    __shared__ float sdiag[128];
    int bi = blockIdx.x;
    int isL = (bi < 32) ? 1 : 0;
    int b = isL ? bi : bi - 32;
    int t = threadIdx.x, wid = t >> 5, lane = t & 31;
    uint32_t buf = smem_u32(dyn);

    if (t < 128) sdiag[t] = diag[t];

    const unsigned char* srcH = isL ? g_Lh : g_Rh;
    const unsigned char* srcL = isL ? g_Ll : g_Rl;

    int wl = wid >> 2, wn = wid & 3;
    float acc[4][4][4];
    #pragma unroll
    for (int i = 0; i < 4; i++)
        #pragma unroll
        for (int j = 0; j < 4; j++)
            #pragma unroll
            for (int k = 0; k < 4; k++) acc[i][j][k] = 0.f;

    int rowA = lane & 15;
    int cbA  = lane >> 4;
    int rowB = ((lane >> 4) & 1) * 8 + (lane & 7);
    int cbB  = (lane >> 3) & 1;

    for (int c = 0; c < 8; c++){
        {
            const unsigned char* ah = srcH + (((size_t)(b*8 + c)) << 14);
            const unsigned char* al = srcL + (((size_t)(b*8 + c)) << 14);
            const unsigned char* wh = g_Wh + (((size_t)c) << 14);
            const unsigned char* wlp = g_Wl + (((size_t)c) << 14);
            #pragma unroll
            for (int i = 0; i < 4; i++){
                uint32_t o = (uint32_t)(i*256 + t) * 16;
                CP16(buf + o,         ah + o);
                CP16(buf + 16384 + o, al + o);
                CP16(buf + 32768 + o, wh + o);
                CP16(buf + 49152 + o, wlp + o);
            }
            CPCOMMIT();
        }
        CPWAIT0();
        __syncthreads();

        uint32_t Ah = buf, Al = buf + 16384, Wh = buf + 32768, Wlb = buf + 49152;
        #pragma unroll
        for (int ks = 0; ks < 4; ks++){
            uint32_t aoffs[4], boffs[2];
            #pragma unroll
            for (int mt = 0; mt < 4; mt++)
                aoffs[mt] = swz((uint32_t)((wl*64 + mt*16 + rowA)*128 + ks*32 + cbA*16));
            #pragma unroll
            for (int jp = 0; jp < 2; jp++)
                boffs[jp] = swz((uint32_t)((wn*32 + jp*16 + rowB)*128 + ks*32 + cbB*16));

            uint32_t bh_[4][2];
            #pragma unroll
            for (int jp = 0; jp < 2; jp++)
                LDSM4(bh_[jp*2][0], bh_[jp*2][1], bh_[jp*2+1][0], bh_[jp*2+1][1], Wh + boffs[jp]);
            {
                uint32_t al_[4][4];
                #pragma unroll
                for (int mt = 0; mt < 4; mt++)
                    LDSM4(al_[mt][0], al_[mt][1], al_[mt][2], al_[mt][3], Al + aoffs[mt]);
                #pragma unroll
                for (int mt = 0; mt < 4; mt++)
                    #pragma unroll
                    for (int nt = 0; nt < 4; nt++)
                        mma_bf16(acc[mt][nt], al_[mt], bh_[nt]);
            }
            uint32_t ah_[4][4];
            #pragma unroll
            for (int mt = 0; mt < 4; mt++)
                LDSM4(ah_[mt][0], ah_[mt][1], ah_[mt][2], ah_[mt][3], Ah + aoffs[mt]);
            #pragma unroll
            for (int mt = 0; mt < 4; mt++)
                #pragma unroll
                for (int nt = 0; nt < 4; nt++)
                    mma_bf16(acc[mt][nt], ah_[mt], bh_[nt]);
            {
                uint32_t bl_[4][2];
                #pragma unroll
                for (int jp = 0; jp < 2; jp++)
                    LDSM4(bl_[jp*2][0], bl_[jp*2][1], bl_[jp*2+1][0], bl_[jp*2+1][1], Wlb + boffs[jp]);
                #pragma unroll
                for (int mt = 0; mt < 4; mt++)
                    #pragma unroll
                    for (int nt = 0; nt < 4; nt++)
                        mma_bf16(acc[mt][nt], ah_[mt], bl_[nt]);
            }
        }
        __syncthreads();
    }

    int g = lane >> 2, tg = lane & 3;
    size_t rbase = (size_t)bi * 128;
    #pragma unroll
    for (int mt = 0; mt < 4; mt++){
        int r0 = wl*64 + mt*16 + g, r1 = r0 + 8;
        #pragma unroll
        for (int nt = 0; nt < 4; nt++){
            int col = wn*32 + nt*8 + tg*2;
            float d0 = isL ? sdiag[col] : 1.f;
            float d1 = isL ? sdiag[col+1] : 1.f;
            float2 v0 = make_float2(tanhf(acc[mt][nt][0])*d0, tanhf(acc[mt][nt][1])*d1);
            float2 v1 = make_float2(tanhf(acc[mt][nt][2])*d0, tanhf(acc[mt][nt][3])*d1);
            *(float2*)&g_algt[(rbase + r0)*A + col] = v0;
            *(float2*)&g_algt[(rbase + r1)*A + col] = v1;
        }
    }
}

// ============================================================================
// k_score v2: register-tiled scores + softmax.  grid (4, B): 32 l x 128 r.
// ============================================================================
__global__ void __launch_bounds__(256) k_score()
{
    __shared__ float Ls[16*36];    // [a][l]
    __shared__ float Rs[16*132];   // [a][r]
    __shared__ float S[32*132];

    int b = blockIdx.y, l0 = blockIdx.x*32, t = threadIdx.x;
    int ly = t >> 4, tx = t & 15;
    float acc[2][8];
    #pragma unroll
    for (int i = 0; i < 2; i++)
        #pragma unroll
        for (int j = 0; j < 8; j++) acc[i][j] = 0.f;

    const float* Lb = g_algt + (size_t)(b*LL + l0) * A;
    const float* Rb = g_algt + (size_t)(B*LL + b*LR) * A;

    for (int kc = 0; kc < 8; kc++){
        __syncthreads();
        {   // L chunk 32 rows x 16 a, transposed
            int row = t >> 3, c2 = (t & 7)*2;
            float2 v = *(const float2*)(Lb + (size_t)row*A + kc*16 + c2);
            Ls[c2*36 + row] = v.x;
            Ls[(c2+1)*36 + row] = v.y;
        }
        {   // R chunk 128 rows x 16 a, transposed
            int row = t >> 1, c8 = (t & 1)*8;
            const float* src = Rb + (size_t)row*A + kc*16 + c8;
            float4 v0 = *(const float4*)src, v1 = *(const float4*)(src + 4);
            Rs[(c8+0)*132 + row] = v0.x; Rs[(c8+1)*132 + row] = v0.y;
            Rs[(c8+2)*132 + row] = v0.z; Rs[(c8+3)*132 + row] = v0.w;
            Rs[(c8+4)*132 + row] = v1.x; Rs[(c8+5)*132 + row] = v1.y;
            Rs[(c8+6)*132 + row] = v1.z; Rs[(c8+7)*132 + row] = v1.w;
        }
        __syncthreads();
        #pragma unroll
        for (int k = 0; k < 16; k++){
            float a0 = Ls[k*36 + ly], a1 = Ls[k*36 + ly + 16];
            float4 b0 = *(const float4*)&Rs[k*132 + tx*8];
            float4 b1 = *(const float4*)&Rs[k*132 + tx*8 + 4];
            float bv[8] = {b0.x,b0.y,b0.z,b0.w,b1.x,b1.y,b1.z,b1.w};
            #pragma unroll
            for (int j = 0; j < 8; j++){
                acc[0][j] = fmaf(a0, bv[j], acc[0][j]);
                acc[1][j] = fmaf(a1, bv[j], acc[1][j]);
            }
        }
    }
    #pragma unroll
    for (int i = 0; i < 2; i++)
        #pragma unroll
        for (int j = 0; j < 8; j++)
            S[(ly + i*16)*132 + tx*8 + j] = acc[i][j];
    __syncthreads();

    // softmax: warp w -> rows 4w..4w+3
    int w = t >> 5, lane = t & 31;
    #pragma unroll
    for (int rr = w*4; rr < w*4 + 4; rr++){
        float v0 = S[rr*132+lane], v1 = S[rr*132+lane+32],
              v2 = S[rr*132+lane+64], v3 = S[rr*132+lane+96];
        float m0 = fmaxf(fmaxf(v0,v1), fmaxf(v2,v3));
        #pragma unroll
        for (int off = 16; off; off >>= 1) m0 = fmaxf(m0, __shfl_xor_sync(0xffffffffu, m0, off));
        float e0 = expf(v0-m0), e1 = expf(v1-m0), e2 = expf(v2-m0), e3 = expf(v3-m0);
        float sum = e0+e1+e2+e3;
        #pragma unroll
        for (int off = 16; off; off >>= 1) sum += __shfl_xor_sync(0xffffffffu, sum, off);
        float inv = 1.f / sum;
        float* pp = g_probs + (size_t)(b*LL + l0 + rr)*LR;
        pp[lane] = e0*inv; pp[lane+32] = e1*inv;
        pp[lane+64] = e2*inv; pp[lane+96] = e3*inv;
    }
}

// ============================================================================
// k_pr: att = P @ R.  grid (32, B), 256 thr.
// ============================================================================
__global__ void __launch_bounds__(256) k_pr(const float* __restrict__ Rr)
{
    __shared__ __align__(16) float P[16*132];
    __shared__ __align__(16) float Rs[16*132];

    int blk = blockIdx.x, b = blockIdx.y;
    int l0 = (blk >> 2)*16, d0 = (blk & 3)*128;
    int t = threadIdx.x;

    #pragma unroll
    for (int i = 0; i < 8; i++){
        int f = i*256 + t; int r = f >> 7, c = f & 127;
        P[r*132 + c] = g_probs[(size_t)(b*LL + l0 + r)*LR + c];
    }

    int l = t >> 4, dq = t & 15;
    float4 acc0 = make_float4(0,0,0,0), acc1 = make_float4(0,0,0,0);
    for (int rc = 0; rc < 8; rc++){
        __syncthreads();
        {
            int r = t >> 4, c8 = (t & 15)*8;
            const float* src = Rr + (size_t)(b*LR + rc*16 + r)*D + d0 + c8;
            *(float4*)&Rs[r*132 + c8]     = *(const float4*)src;
            *(float4*)&Rs[r*132 + c8 + 4] = *(const float4*)(src + 4);
        }
        __syncthreads();
        #pragma unroll
        for (int r = 0; r < 16; r++){
            float p = P[l*132 + rc*16 + r];
            float4 v0 = *(const float4*)&Rs[r*132 + dq*8];
            float4 v1 = *(const float4*)&Rs[r*132 + dq*8 + 4];
            acc0.x = fmaf(p, v0.x, acc0.x); acc0.y = fmaf(p, v0.y, acc0.y);
            acc0.z = fmaf(p, v0.z, acc0.z); acc0.w = fmaf(p, v0.w, acc0.w);
            acc1.x = fmaf(p, v1.x, acc1.x); acc1.y = fmaf(p, v1.y, acc1.y);
            acc1.z = fmaf(p, v1.z, acc1.z); acc1.w = fmaf(p, v1.w, acc1.w);
        }
    }
    float* op = g_att + (size_t)(b*LL + l0 + l)*D + d0 + dq*8;
    *(float4*)op = acc0; *(float4*)(op + 4) = acc1;
}

// ============================================================================
// k_nrt: inv right norms, grid 512 (one warp per row)
// ============================================================================
__global__ void k_nrt(const float* __restrict__ Rr)
{
    int blk = blockIdx.x;
    int b = blk >> 4, r = (blk & 15)*8 + (threadIdx.x >> 5);
    int lane = threadIdx.x & 31;
    const float* row = Rr + (size_t)(b*LR + r) * D;
    float s = 0.f;
    #pragma unroll 4
    for (int i = lane; i < D; i += 32){ float v = row[i]; s = fmaf(v, v, s); }
    #pragma unroll
    for (int off = 16; off; off >>= 1) s += __shfl_xor_sync(0xffffffffu, s, off);
    if (!lane) g_invnrt[b*LR + r] = rsqrtf(fmaxf(s, 1e-6f));
}

// ============================================================================
// k_idx: argmax_r cosine(L[l], R[r]).  block = 32 l x 128 r, grid (4, B).
// ============================================================================
__global__ void __launch_bounds__(256) k_idx(
    const float* __restrict__ Lr, const float* __restrict__ Rr)
{
    __shared__ float Ls[16*36];
    __shared__ float Rs[16*132];
    __shared__ float sn[128];
    __shared__ float redv[32*17];
    __shared__ int   redi[32*17];

    int b = blockIdx.y, l0 = blockIdx.x*32, t = threadIdx.x;
    if (t < 128) sn[t] = g_invnrt[b*LR + t];

    int ly = t >> 4, tx = t & 15;
    float acc[2][8];
    #pragma unroll
    for (int i = 0; i < 2; i++)
        #pragma unroll
        for (int j = 0; j < 8; j++) acc[i][j] = 0.f;

    const float* Lb = Lr + (size_t)(b*LL + l0) * D;
    const float* Rb = Rr + ((size_t)b << 16);

    for (int kc = 0; kc < 32; kc++){
        __syncthreads();
        {
            int row = t >> 3, c2 = (t & 7)*2;
            float2 v = *(const float2*)(Lb + (size_t)row*D + kc*16 + c2);
            Ls[c2*36 + row] = v.x;
            Ls[(c2+1)*36 + row] = v.y;
        }
        {
            int row = t >> 1, c8 = (t & 1)*8;
            const float* src = Rb + (size_t)row*D + kc*16 + c8;
            float4 v0 = *(const float4*)src, v1 = *(const float4*)(src + 4);
            Rs[(c8+0)*132 + row] = v0.x; Rs[(c8+1)*132 + row] = v0.y;
            Rs[(c8+2)*132 + row] = v0.z; Rs[(c8+3)*132 + row] = v0.w;
            Rs[(c8+4)*132 + row] = v1.x; Rs[(c8+5)*132 + row] = v1.y;
            Rs[(c8+6)*132 + row] = v1.z; Rs[(c8+7)*132 + row] = v1.w;
        }
        __syncthreads();
        #pragma unroll
        for (int k = 0; k < 16; k++){
            float a0 = Ls[k*36 + ly], a1 = Ls[k*36 + ly + 16];
            float4 b0 = *(const float4*)&Rs[k*132 + tx*8];
            float4 b1 = *(const float4*)&Rs[k*132 + tx*8 + 4];
            float bv[8] = {b0.x,b0.y,b0.z,b0.w,b1.x,b1.y,b1.z,b1.w};
            #pragma unroll
            for (int j = 0; j < 8; j++){
                acc[0][j] = fmaf(a0, bv[j], acc[0][j]);
                acc[1][j] = fmaf(a1, bv[j], acc[1][j]);
            }
        }
    }
    #pragma unroll
    for (int i = 0; i < 2; i++){
        float bv = -1e30f; int bi = 0;
        #pragma unroll
        for (int j = 0; j < 8; j++){
            float v = acc[i][j] * sn[tx*8 + j];
            if (v > bv){ bv = v; bi = tx*8 + j; }
        }
        redv[(ly + i*16)*17 + tx] = bv;
        redi[(ly + i*16)*17 + tx] = bi;
    }
    __syncthreads();
    if (t < 32){
        float bv = -1e30f; int bi = 0;
        #pragma unroll
        for (int j = 0; j < 16; j++){
            float v = redv[t*17 + j];
            if (v > bv){ bv = v; bi = redi[t*17 + j]; }
        }
        g_idx[b*LL + l0 + t] = bi;
    }
}

// ============================================================================
// k_mp3: one mp_match epilogue (mode per launch).  grid 256.
// ============================================================================
__global__ void __launch_bounds__(256) k_mp3(
    const float* __restrict__ Lr, const float* __restrict__ hfw,
    const float* __restrict__ hbw, const float* __restrict__ Kmat,
    const float* __restrict__ Rr, float* __restrict__ out,
    int mode, int col0)
{
    __shared__ __align__(16) float P[16][68];
    __shared__ __align__(16) float Kc[64][68];
    __shared__ float hv[512];
    __shared__ float red[16][65];
    __shared__ int   sidx[16];

    int blk = blockIdx.x;
    int b = blk >> 3, l0 = (blk & 7) * 16;
    int t = threadIdx.x;

    if (mode == 0) { hv[t] = hfw[b*256 + t]; hv[256 + t] = hbw[b*256 + t]; }
    if (mode == 2 && t < 16) sidx[t] = g_idx[b*LL + l0 + t];

    int li = t >> 4, mj = t & 15;
    int srow = t >> 6, sk = t & 63;
    float cacc[4] = {0.f, 0.f, 0.f, 0.f};
    float acc[4]  = {0.f, 0.f, 0.f, 0.f};
    __syncthreads();

    for (int c = 0; c < 8; c++) {
        #pragma unroll
        for (int i = 0; i < 16; i++) {
            int f = i * 256 + t; int m = f >> 6, k = f & 63;
            Kc[m][k] = Kmat[(size_t)m * D + c*64 + k];
        }
        #pragma unroll
        for (int i = 0; i < 4; i++) {
            int row = i*4 + srow;
            int gl = b*LL + l0 + row;
            float lv = Lr[(size_t)gl * D + c*64 + sk];
            float av;
            if (mode == 0)      av = hv[c*64 + sk];
            else if (mode == 1) av = g_att[(size_t)gl * D + c*64 + sk];
            else                av = Rr[(size_t)(b*LR + sidx[row]) * D + c*64 + sk];
            float p = lv * av;
            P[row][sk] = p;
            cacc[i] += p;
        }
        __syncthreads();
        #pragma unroll
        for (int k4 = 0; k4 < 16; k4++) {
            float4 p4 = *(const float4*)&P[li][k4*4];
            #pragma unroll
            for (int j = 0; j < 4; j++) {
                float4 kv = *(const float4*)&Kc[j*16 + mj][k4*4];
                acc[j] = fmaf(p4.x, kv.x, fmaf(p4.y, kv.y, fmaf(p4.z, kv.z, fmaf(p4.w, kv.w, acc[j]))));
            }
        }
        __syncthreads();
    }
    #pragma unroll
    for (int i = 0; i < 4; i++) red[i*4 + srow][sk] = cacc[i];
    __syncthreads();
    if (t < 16) {
        float s = 0.f;
        #pragma unroll
        for (int k = 0; k < 64; k++) s += red[t][k];
        out[(size_t)(b*LL + l0 + t) * OC + col0] = tanhf(s);
    }
    #pragma unroll
    for (int j = 0; j < 4; j++)
        out[(size_t)(b*LL + l0 + li) * OC + col0 + 1 + j*16 + mj] = tanhf(acc[j]);
}

// ============================================================================
extern "C" void kernel_launch(void* const* d_in, const int* in_sizes, int n_in,
                              void* d_out, int out_size)
{
    const float* reps_lt = (const float*)d_in[0];
    const float* reps_rt = (const float*)d_in[3];
    const float* h_rt_fw = (const float*)d_in[4];
    const float* h_rt_bw = (const float*)d_in[5];
    const float* k_full  = (const float*)d_in[6];
    const float* k_mpW   = (const float*)d_in[7];
    const float* attn_w1 = (const float*)d_in[8];
    const float* diag_w  = (const float*)d_in[9];
    const float* k_attW  = (const float*)d_in[10];
    const float* k_maxW  = (const float*)d_in[11];
    float* out = (float*)d_out;

    static cudaStream_t s2 = 0, s3 = 0;
    static cudaEvent_t  eF = 0, eJ2 = 0, eJ3 = 0;
    if (!s2) {
        cudaFuncSetAttribute(k_mpool_mma, cudaFuncAttributeMaxDynamicSharedMemorySize, 116736);
        cudaFuncSetAttribute(k_algt_mma,  cudaFuncAttributeMaxDynamicSharedMemorySize, 65536);
        cudaStreamCreateWithFlags(&s2, cudaStreamNonBlocking);
        cudaStreamCreateWithFlags(&s3, cudaStreamNonBlocking);
        cudaEventCreateWithFlags(&eF,  cudaEventDisableTiming);
        cudaEventCreateWithFlags(&eJ2, cudaEventDisableTiming);
        cudaEventCreateWithFlags(&eJ3, cudaEventDisableTiming);
    }

    // main: split L first (needed by mpool AND algt_mma), then fork
    k_split<<<dim3(8, B), 256>>>(reps_lt, 0);
    cudaEventRecord(eF, 0);
    cudaStreamWaitEvent(s2, eF, 0);
    cudaStreamWaitEvent(s3, eF, 0);

    // main stream: dominant tensor-core chain (cols 65..128), occ-1 by smem
    k_mpool_mma<<<dim3(64, B), 256, 116736>>>(reps_rt, k_mpW, out);

    // s2: attentive path -> mp3 mode1 (cols 129..193)
    k_split<<<dim3(8, B), 256, 0, s2>>>(reps_rt, 1);
    k_splitW<<<8, 256, 0, s2>>>(attn_w1);
    k_algt_mma<<<64, 256, 65536, s2>>>(diag_w);
    k_score<<<dim3(4, B), 256, 0, s2>>>();
    k_pr<<<dim3(32, B), 256, 0, s2>>>(reps_rt);
    k_mp3<<<256, 256, 0, s2>>>(reps_lt, h_rt_fw, h_rt_bw, k_attW, reps_rt, out, 1, 129);

    // s3: full match (cols 0..64) + max-attentive -> mp3 mode2 (cols 194..258)
    k_mp3<<<256, 256, 0, s3>>>(reps_lt, h_rt_fw, h_rt_bw, k_full, reps_rt, out, 0, 0);
    k_nrt<<<512, 256, 0, s3>>>(reps_rt);
    k_idx<<<dim3(4, B), 256, 0, s3>>>(reps_lt, reps_rt);
    k_mp3<<<256, 256, 0, s3>>>(reps_lt, h_rt_fw, h_rt_bw, k_maxW, reps_rt, out, 2, 194);

    // join side streams back into the main stream
    cudaEventRecord(eJ2, s2);
    cudaEventRecord(eJ3, s3);
    cudaStreamWaitEvent(0, eJ2, 0);
    cudaStreamWaitEvent(0, eJ3, 0);
}

// round 12
// speedup vs baseline: 1.1453x; 1.1453x over previous
#include <cuda_runtime.h>
#include <math.h>
#include <stdint.h>

#define B   32
#define LL  128
#define LR  128
#define D   512
#define A   128
#define OC  259   // 1+64 | 64 | 1+64 | 1+64

// ---- scratch (static device globals; no runtime allocation) ----
__device__ float g_algt[(B*LL + B*LR) * A];
__device__ float g_att[B*LL*D];
__device__ float g_probs[B*LL*LR];
__device__ float g_invnrt[B*LR];
__device__ int   g_idx[B*LL];
// pre-split bf16 hi/lo swizzled tiles: (b,chunk) tiles of 128 rows x 128B
__device__ __align__(16) unsigned char g_Lh[B*8*16384];
__device__ __align__(16) unsigned char g_Ll[B*8*16384];
__device__ __align__(16) unsigned char g_Rh[B*8*16384];
__device__ __align__(16) unsigned char g_Rl[B*8*16384];
// W1 transposed to B-operand tiles: 8 chunks x (128 a-rows x 64 d) hi/lo
__device__ __align__(16) unsigned char g_Wh[8*16384];
__device__ __align__(16) unsigned char g_Wl[8*16384];

__device__ __forceinline__ uint32_t swz(uint32_t x){ return x ^ ((x >> 3) & 0x70u); }
__device__ __forceinline__ uint32_t smem_u32(const void* p){
    uint32_t a;
    asm("{ .reg .u64 t; cvta.to.shared.u64 t, %1; cvt.u32.u64 %0, t; }" : "=r"(a) : "l"(p));
    return a;
}
__device__ __forceinline__ void split2(float x0, float x1, uint32_t& h, uint32_t& l){
    asm("cvt.rn.bf16x2.f32 %0, %1, %2;" : "=r"(h) : "f"(x1), "f"(x0));
    float h0 = __uint_as_float(h << 16), h1 = __uint_as_float(h & 0xffff0000u);
    asm("cvt.rn.bf16x2.f32 %0, %1, %2;" : "=r"(l) : "f"(x1 - h1), "f"(x0 - h0));
}

#define LDSM4(r0,r1,r2,r3,addr) \
    asm volatile("ldmatrix.sync.aligned.m8n8.x4.shared.b16 {%0,%1,%2,%3}, [%4];" \
        : "=r"(r0),"=r"(r1),"=r"(r2),"=r"(r3) : "r"(addr))
#define CP16(s,g) \
    asm volatile("cp.async.cg.shared.global [%0], [%1], 16;" :: "r"(s), "l"(g))
#define CPCOMMIT() asm volatile("cp.async.commit_group;")
#define CPWAIT1()  asm volatile("cp.async.wait_group 1;")
#define CPWAIT0()  asm volatile("cp.async.wait_group 0;")

__device__ __forceinline__ void mma_bf16(float* d, const uint32_t* a, const uint32_t* b){
    asm volatile("mma.sync.aligned.m16n8k16.row.col.f32.bf16.bf16.f32 "
        "{%0,%1,%2,%3}, {%4,%5,%6,%7}, {%8,%9}, {%0,%1,%2,%3};"
        : "+f"(d[0]),"+f"(d[1]),"+f"(d[2]),"+f"(d[3])
        : "r"(a[0]),"r"(a[1]),"r"(a[2]),"r"(a[3]), "r"(b[0]),"r"(b[1]));
}

// ============================================================================
// k_split: X (fp32) -> hi/lo bf16 swizzled tiles. grid (8, B). which: 0=L 1=R
// ============================================================================
__global__ void __launch_bounds__(256) k_split(const float* __restrict__ X, int which)
{
    int c = blockIdx.x, b = blockIdx.y, t = threadIdx.x;
    const float* Xb = X + ((size_t)b << 16) + c*64;
    size_t tile = ((size_t)(b*8 + c)) << 14;
    unsigned char* dh = (which ? g_Rh : g_Lh) + tile;
    unsigned char* dl = (which ? g_Rl : g_Ll) + tile;
    #pragma unroll
    for (int i = 0; i < 4; i++){
        int f = i*256 + t; int row = f >> 3, q = f & 7;
        const float* src = Xb + (size_t)row*512 + q*8;
        float4 v0 = *(const float4*)src, v1 = *(const float4*)(src + 4);
        uint32_t h01,l01,h23,l23,h45,l45,h67,l67;
        split2(v0.x, v0.y, h01, l01);
        split2(v0.z, v0.w, h23, l23);
        split2(v1.x, v1.y, h45, l45);
        split2(v1.z, v1.w, h67, l67);
        uint32_t off = swz((uint32_t)(row*128 + q*16));
        *(uint4*)(dh + off) = make_uint4(h01, h23, h45, h67);
        *(uint4*)(dl + off) = make_uint4(l01, l23, l45, l67);
    }
}

// ============================================================================
// k_splitW: W1 [d=512][a=128] -> transposed B tiles. grid (8, 8).
// ============================================================================
__global__ void __launch_bounds__(256) k_splitW(const float* __restrict__ W1)
{
    int c = blockIdx.x, t = threadIdx.x;
    size_t tile = ((size_t)c) << 14;
    int i = blockIdx.y;
    {
        int f = i*256 + t; int row = f >> 4, q = f & 15;
        int d0 = c*64 + q*4;
        float w0 = W1[(size_t)(d0+0)*A + row];
        float w1 = W1[(size_t)(d0+1)*A + row];
        float w2 = W1[(size_t)(d0+2)*A + row];
        float w3 = W1[(size_t)(d0+3)*A + row];
        uint32_t h01,l01,h23,l23;
        split2(w0, w1, h01, l01);
        split2(w2, w3, h23, l23);
        uint32_t off = swz((uint32_t)(row*128 + q*8));
        *(uint2*)(g_Wh + tile + off) = make_uint2(h01, h23);
        *(uint2*)(g_Wl + tile + off) = make_uint2(l01, l23);
    }
}

// ============================================================================
// k_mpool_mma (R8/R10 version): CTA = (m, b).
// C[l,r] = sum_d L[l,d]*(R[r,d]*K_m[d]); out[b,l,65+m] = tanh(max_r C).
// dyn smem 100352 B, occ 2.
// ============================================================================
__global__ void __launch_bounds__(256, 2) k_mpool_mma(
    const float* __restrict__ Rr, const float* __restrict__ Kmp,
    float* __restrict__ out)
{
    extern __shared__ __align__(16) unsigned char dyn[];
    int m = blockIdx.x, b = blockIdx.y;
    int t = threadIdx.x, wid = t >> 5, lane = t & 31;
    uint32_t base = smem_u32(dyn);
    uint32_t Abuf[2] = {base, base + 32768};
    uint32_t Bh = base + 65536, Bl = base + 81920;
    float* sK = (float*)(dyn + 98304);
    for (int i = t; i < 512; i += 256) sK[i] = Kmp[(size_t)m*512 + i];

    {
        const unsigned char* gh = g_Lh + (((size_t)(b*8)) << 14);
        const unsigned char* gl = g_Ll + (((size_t)(b*8)) << 14);
        #pragma unroll
        for (int i = 0; i < 4; i++){
            uint32_t o = (uint32_t)(i*256 + t) * 16;
            CP16(Abuf[0] + o, gh + o);
            CP16(Abuf[0] + 16384 + o, gl + o);
        }
        CPCOMMIT();
    }
    __syncthreads();

    int wl = wid >> 2, wn = wid & 3;
    float acc[4][4][4];
    #pragma unroll
    for (int i = 0; i < 4; i++)
        #pragma unroll
        for (int j = 0; j < 4; j++)
            #pragma unroll
            for (int k = 0; k < 4; k++) acc[i][j][k] = 0.f;

    int rowA = lane & 15;
    int cbA  = lane >> 4;
    int rowB = ((lane >> 4) & 1) * 8 + (lane & 7);
    int cbB  = (lane >> 3) & 1;

    const float* Rb = Rr + ((size_t)b << 16);
    int rrow = t >> 3, rq = t & 7;

    for (int c = 0; c < 8; c++){
        if (c < 7){
            uint32_t nb = Abuf[(c+1) & 1];
            const unsigned char* gh = g_Lh + (((size_t)(b*8 + c+1)) << 14);
            const unsigned char* gl = g_Ll + (((size_t)(b*8 + c+1)) << 14);
            #pragma unroll
            for (int i = 0; i < 4; i++){
                uint32_t o = (uint32_t)(i*256 + t) * 16;
                CP16(nb + o, gh + o);
                CP16(nb + 16384 + o, gl + o);
            }
            CPCOMMIT();
        }
        {
            float4 k0 = *(const float4*)(sK + c*64 + rq*8);
            float4 k1 = *(const float4*)(sK + c*64 + rq*8 + 4);
            #pragma unroll
            for (int i = 0; i < 4; i++){
                int row = rrow + i*32;
                const float* src = Rb + (size_t)row*512 + c*64 + rq*8;
                float4 r0 = *(const float4*)src, r1 = *(const float4*)(src + 4);
                uint32_t h01,l01,h23,l23,h45,l45,h67,l67;
                split2(r0.x*k0.x, r0.y*k0.y, h01, l01);
                split2(r0.z*k0.z, r0.w*k0.w, h23, l23);
                split2(r1.x*k1.x, r1.y*k1.y, h45, l45);
                split2(r1.z*k1.z, r1.w*k1.w, h67, l67);
                uint32_t off = swz((uint32_t)(row*128 + rq*16));
                asm volatile("st.shared.v4.b32 [%0], {%1,%2,%3,%4};"
                             :: "r"(Bh+off), "r"(h01), "r"(h23), "r"(h45), "r"(h67));
                asm volatile("st.shared.v4.b32 [%0], {%1,%2,%3,%4};"
                             :: "r"(Bl+off), "r"(l01), "r"(l23), "r"(l45), "r"(l67));
            }
        }
        if (c < 7) { CPWAIT1(); } else { CPWAIT0(); }
        __syncthreads();

        uint32_t Ah = Abuf[c & 1], Al = Ah + 16384;
        #pragma unroll
        for (int ks = 0; ks < 4; ks++){
            uint32_t aoffs[4], boffs[2];
            #pragma unroll
            for (int mt = 0; mt < 4; mt++)
                aoffs[mt] = swz((uint32_t)((wl*64 + mt*16 + rowA)*128 + ks*32 + cbA*16));
            #pragma unroll
            for (int jp = 0; jp < 2; jp++)
                boffs[jp] = swz((uint32_t)((wn*32 + jp*16 + rowB)*128 + ks*32 + cbB*16));

            uint32_t bh_[4][2];
            #pragma unroll
            for (int jp = 0; jp < 2; jp++)
                LDSM4(bh_[jp*2][0], bh_[jp*2][1], bh_[jp*2+1][0], bh_[jp*2+1][1], Bh + boffs[jp]);
            {
                uint32_t al_[4][4];
                #pragma unroll
                for (int mt = 0; mt < 4; mt++)
                    LDSM4(al_[mt][0], al_[mt][1], al_[mt][2], al_[mt][3], Al + aoffs[mt]);
                #pragma unroll
                for (int mt = 0; mt < 4; mt++)
                    #pragma unroll
                    for (int nt = 0; nt < 4; nt++)
                        mma_bf16(acc[mt][nt], al_[mt], bh_[nt]);
            }
            uint32_t ah_[4][4];
            #pragma unroll
            for (int mt = 0; mt < 4; mt++)
                LDSM4(ah_[mt][0], ah_[mt][1], ah_[mt][2], ah_[mt][3], Ah + aoffs[mt]);
            #pragma unroll
            for (int mt = 0; mt < 4; mt++)
                #pragma unroll
                for (int nt = 0; nt < 4; nt++)
                    mma_bf16(acc[mt][nt], ah_[mt], bh_[nt]);
            {
                uint32_t bl_[4][2];
                #pragma unroll
                for (int jp = 0; jp < 2; jp++)
                    LDSM4(bl_[jp*2][0], bl_[jp*2][1], bl_[jp*2+1][0], bl_[jp*2+1][1], Bl + boffs[jp]);
                #pragma unroll
                for (int mt = 0; mt < 4; mt++)
                    #pragma unroll
                    for (int nt = 0; nt < 4; nt++)
                        mma_bf16(acc[mt][nt], ah_[mt], bl_[nt]);
            }
        }
        __syncthreads();
    }

    float* red = (float*)dyn;
    int g = lane >> 2, tg = lane & 3;
    #pragma unroll
    for (int mt = 0; mt < 4; mt++){
        float m0 = -1e30f, m1 = -1e30f;
        #pragma unroll
        for (int nt = 0; nt < 4; nt++){
            m0 = fmaxf(m0, fmaxf(acc[mt][nt][0], acc[mt][nt][1]));
            m1 = fmaxf(m1, fmaxf(acc[mt][nt][2], acc[mt][nt][3]));
        }
        m0 = fmaxf(m0, __shfl_xor_sync(0xffffffffu, m0, 1));
        m0 = fmaxf(m0, __shfl_xor_sync(0xffffffffu, m0, 2));
        m1 = fmaxf(m1, __shfl_xor_sync(0xffffffffu, m1, 1));
        m1 = fmaxf(m1, __shfl_xor_sync(0xffffffffu, m1, 2));
        if (tg == 0){
            red[(wl*64 + mt*16 + g)*4 + wn]     = m0;
            red[(wl*64 + mt*16 + g + 8)*4 + wn] = m1;
        }
    }
    __syncthreads();
    if (t < 128){
        float v = fmaxf(fmaxf(red[t*4], red[t*4+1]), fmaxf(red[t*4+2], red[t*4+3]));
        out[((size_t)(b*LL + t))*OC + 65 + m] = tanhf(v);
    }
}

// ============================================================================
// k_algt_mma (R10 version): tanh([L;R] @ W1) (*diag for L rows).
// grid 64, 256 thr.  Double-buffered: dyn smem 131072 B.
// ============================================================================
__global__ void __launch_bounds__(256) k_algt_mma(const float* __restrict__ diag)
{
    extern __shared__ __align__(16) unsigned char dyn[];
    __shared__ float sdiag[128];
    int bi = blockIdx.x;
    int isL = (bi < 32) ? 1 : 0;
    int b = isL ? bi : bi - 32;
    int t = threadIdx.x, wid = t >> 5, lane = t & 31;
    uint32_t base = smem_u32(dyn);
    uint32_t buf[2] = {base, base + 65536};

    if (t < 128) sdiag[t] = diag[t];

    const unsigned char* srcH = isL ? g_Lh : g_Rh;
    const unsigned char* srcL = isL ? g_Ll : g_Rl;

    {
        const unsigned char* ah = srcH + (((size_t)(b*8)) << 14);
        const unsigned char* al = srcL + (((size_t)(b*8)) << 14);
        #pragma unroll
        for (int i = 0; i < 4; i++){
            uint32_t o = (uint32_t)(i*256 + t) * 16;
            CP16(buf[0] + o,         ah + o);
            CP16(buf[0] + 16384 + o, al + o);
            CP16(buf[0] + 32768 + o, g_Wh + o);
            CP16(buf[0] + 49152 + o, g_Wl + o);
        }
        CPCOMMIT();
    }

    int wl = wid >> 2, wn = wid & 3;
    float acc[4][4][4];
    #pragma unroll
    for (int i = 0; i < 4; i++)
        #pragma unroll
        for (int j = 0; j < 4; j++)
            #pragma unroll
            for (int k = 0; k < 4; k++) acc[i][j][k] = 0.f;

    int rowA = lane & 15;
    int cbA  = lane >> 4;
    int rowB = ((lane >> 4) & 1) * 8 + (lane & 7);
    int cbB  = (lane >> 3) & 1;

    for (int c = 0; c < 8; c++){
        if (c < 7){
            uint32_t nb = buf[(c+1) & 1];
            const unsigned char* ah = srcH + (((size_t)(b*8 + c+1)) << 14);
            const unsigned char* al = srcL + (((size_t)(b*8 + c+1)) << 14);
            const unsigned char* wh = g_Wh + (((size_t)(c+1)) << 14);
            const unsigned char* wlp = g_Wl + (((size_t)(c+1)) << 14);
            #pragma unroll
            for (int i = 0; i < 4; i++){
                uint32_t o = (uint32_t)(i*256 + t) * 16;
                CP16(nb + o,         ah + o);
                CP16(nb + 16384 + o, al + o);
                CP16(nb + 32768 + o, wh + o);
                CP16(nb + 49152 + o, wlp + o);
            }
            CPCOMMIT();
        }
        if (c < 7) { CPWAIT1(); } else { CPWAIT0(); }
        __syncthreads();

        uint32_t Ah = buf[c & 1], Al = Ah + 16384, Wh = Ah + 32768, Wlb = Ah + 49152;
        #pragma unroll
        for (int ks = 0; ks < 4; ks++){
            uint32_t aoffs[4], boffs[2];
            #pragma unroll
            for (int mt = 0; mt < 4; mt++)
                aoffs[mt] = swz((uint32_t)((wl*64 + mt*16 + rowA)*128 + ks*32 + cbA*16));
            #pragma unroll
            for (int jp = 0; jp < 2; jp++)
                boffs[jp] = swz((uint32_t)((wn*32 + jp*16 + rowB)*128 + ks*32 + cbB*16));

            uint32_t bh_[4][2];
            #pragma unroll
            for (int jp = 0; jp < 2; jp++)
                LDSM4(bh_[jp*2][0], bh_[jp*2][1], bh_[jp*2+1][0], bh_[jp*2+1][1], Wh + boffs[jp]);
            {
                uint32_t al_[4][4];
                #pragma unroll
                for (int mt = 0; mt < 4; mt++)
                    LDSM4(al_[mt][0], al_[mt][1], al_[mt][2], al_[mt][3], Al + aoffs[mt]);
                #pragma unroll
                for (int mt = 0; mt < 4; mt++)
                    #pragma unroll
                    for (int nt = 0; nt < 4; nt++)
                        mma_bf16(acc[mt][nt], al_[mt], bh_[nt]);
            }
            uint32_t ah_[4][4];
            #pragma unroll
            for (int mt = 0; mt < 4; mt++)
                LDSM4(ah_[mt][0], ah_[mt][1], ah_[mt][2], ah_[mt][3], Ah + aoffs[mt]);
            #pragma unroll
            for (int mt = 0; mt < 4; mt++)
                #pragma unroll
                for (int nt = 0; nt < 4; nt++)
                    mma_bf16(acc[mt][nt], ah_[mt], bh_[nt]);
            {
                uint32_t bl_[4][2];
                #pragma unroll
                for (int jp = 0; jp < 2; jp++)
                    LDSM4(bl_[jp*2][0], bl_[jp*2][1], bl_[jp*2+1][0], bl_[jp*2+1][1], Wlb + boffs[jp]);
                #pragma unroll
                for (int mt = 0; mt < 4; mt++)
                    #pragma unroll
                    for (int nt = 0; nt < 4; nt++)
                        mma_bf16(acc[mt][nt], ah_[mt], bl_[nt]);
            }
        }
        __syncthreads();
    }

    int g = lane >> 2, tg = lane & 3;
    size_t rbase = (size_t)bi * 128;
    #pragma unroll
    for (int mt = 0; mt < 4; mt++){
        int r0 = wl*64 + mt*16 + g, r1 = r0 + 8;
        #pragma unroll
        for (int nt = 0; nt < 4; nt++){
            int col = wn*32 + nt*8 + tg*2;
            float d0 = isL ? sdiag[col] : 1.f;
            float d1 = isL ? sdiag[col+1] : 1.f;
            float2 v0 = make_float2(tanhf(acc[mt][nt][0])*d0, tanhf(acc[mt][nt][1])*d1);
            float2 v1 = make_float2(tanhf(acc[mt][nt][2])*d0, tanhf(acc[mt][nt][3])*d1);
            *(float2*)&g_algt[(rbase + r0)*A + col] = v0;
            *(float2*)&g_algt[(rbase + r1)*A + col] = v1;
        }
    }
}

// ============================================================================
// k_score v2: register-tiled scores + softmax.  grid (4, B): 32 l x 128 r.
// ============================================================================
__global__ void __launch_bounds__(256) k_score()
{
    __shared__ float Ls[16*36];    // [a][l]
    __shared__ float Rs[16*132];   // [a][r]
    __shared__ float S[32*132];

    int b = blockIdx.y, l0 = blockIdx.x*32, t = threadIdx.x;
    int ly = t >> 4, tx = t & 15;
    float acc[2][8];
    #pragma unroll
    for (int i = 0; i < 2; i++)
        #pragma unroll
        for (int j = 0; j < 8; j++) acc[i][j] = 0.f;

    const float* Lb = g_algt + (size_t)(b*LL + l0) * A;
    const float* Rb = g_algt + (size_t)(B*LL + b*LR) * A;

    for (int kc = 0; kc < 8; kc++){
        __syncthreads();
        {
            int row = t >> 3, c2 = (t & 7)*2;
            float2 v = *(const float2*)(Lb + (size_t)row*A + kc*16 + c2);
            Ls[c2*36 + row] = v.x;
            Ls[(c2+1)*36 + row] = v.y;
        }
        {
            int row = t >> 1, c8 = (t & 1)*8;
            const float* src = Rb + (size_t)row*A + kc*16 + c8;
            float4 v0 = *(const float4*)src, v1 = *(const float4*)(src + 4);
            Rs[(c8+0)*132 + row] = v0.x; Rs[(c8+1)*132 + row] = v0.y;
            Rs[(c8+2)*132 + row] = v0.z; Rs[(c8+3)*132 + row] = v0.w;
            Rs[(c8+4)*132 + row] = v1.x; Rs[(c8+5)*132 + row] = v1.y;
            Rs[(c8+6)*132 + row] = v1.z; Rs[(c8+7)*132 + row] = v1.w;
        }
        __syncthreads();
        #pragma unroll
        for (int k = 0; k < 16; k++){
            float a0 = Ls[k*36 + ly], a1 = Ls[k*36 + ly + 16];
            float4 b0 = *(const float4*)&Rs[k*132 + tx*8];
            float4 b1 = *(const float4*)&Rs[k*132 + tx*8 + 4];
            float bv[8] = {b0.x,b0.y,b0.z,b0.w,b1.x,b1.y,b1.z,b1.w};
            #pragma unroll
            for (int j = 0; j < 8; j++){
                acc[0][j] = fmaf(a0, bv[j], acc[0][j]);
                acc[1][j] = fmaf(a1, bv[j], acc[1][j]);
            }
        }
    }
    #pragma unroll
    for (int i = 0; i < 2; i++)
        #pragma unroll
        for (int j = 0; j < 8; j++)
            S[(ly + i*16)*132 + tx*8 + j] = acc[i][j];
    __syncthreads();

    int w = t >> 5, lane = t & 31;
    #pragma unroll
    for (int rr = w*4; rr < w*4 + 4; rr++){
        float v0 = S[rr*132+lane], v1 = S[rr*132+lane+32],
              v2 = S[rr*132+lane+64], v3 = S[rr*132+lane+96];
        float m0 = fmaxf(fmaxf(v0,v1), fmaxf(v2,v3));
        #pragma unroll
        for (int off = 16; off; off >>= 1) m0 = fmaxf(m0, __shfl_xor_sync(0xffffffffu, m0, off));
        float e0 = expf(v0-m0), e1 = expf(v1-m0), e2 = expf(v2-m0), e3 = expf(v3-m0);
        float sum = e0+e1+e2+e3;
        #pragma unroll
        for (int off = 16; off; off >>= 1) sum += __shfl_xor_sync(0xffffffffu, sum, off);
        float inv = 1.f / sum;
        float* pp = g_probs + (size_t)(b*LL + l0 + rr)*LR;
        pp[lane] = e0*inv; pp[lane+32] = e1*inv;
        pp[lane+64] = e2*inv; pp[lane+96] = e3*inv;
    }
}

// ============================================================================
// k_pr: att = P @ R.  grid (32, B), 256 thr.
// ============================================================================
__global__ void __launch_bounds__(256) k_pr(const float* __restrict__ Rr)
{
    __shared__ __align__(16) float P[16*132];
    __shared__ __align__(16) float Rs[16*132];

    int blk = blockIdx.x, b = blockIdx.y;
    int l0 = (blk >> 2)*16, d0 = (blk & 3)*128;
    int t = threadIdx.x;

    #pragma unroll
    for (int i = 0; i < 8; i++){
        int f = i*256 + t; int r = f >> 7, c = f & 127;
        P[r*132 + c] = g_probs[(size_t)(b*LL + l0 + r)*LR + c];
    }

    int l = t >> 4, dq = t & 15;
    float4 acc0 = make_float4(0,0,0,0), acc1 = make_float4(0,0,0,0);
    for (int rc = 0; rc < 8; rc++){
        __syncthreads();
        {
            int r = t >> 4, c8 = (t & 15)*8;
            const float* src = Rr + (size_t)(b*LR + rc*16 + r)*D + d0 + c8;
            *(float4*)&Rs[r*132 + c8]     = *(const float4*)src;
            *(float4*)&Rs[r*132 + c8 + 4] = *(const float4*)(src + 4);
        }
        __syncthreads();
        #pragma unroll
        for (int r = 0; r < 16; r++){
            float p = P[l*132 + rc*16 + r];
            float4 v0 = *(const float4*)&Rs[r*132 + dq*8];
            float4 v1 = *(const float4*)&Rs[r*132 + dq*8 + 4];
            acc0.x = fmaf(p, v0.x, acc0.x); acc0.y = fmaf(p, v0.y, acc0.y);
            acc0.z = fmaf(p, v0.z, acc0.z); acc0.w = fmaf(p, v0.w, acc0.w);
            acc1.x = fmaf(p, v1.x, acc1.x); acc1.y = fmaf(p, v1.y, acc1.y);
            acc1.z = fmaf(p, v1.z, acc1.z); acc1.w = fmaf(p, v1.w, acc1.w);
        }
    }
    float* op = g_att + (size_t)(b*LL + l0 + l)*D + d0 + dq*8;
    *(float4*)op = acc0; *(float4*)(op + 4) = acc1;
}

// ============================================================================
// k_nrt: inv right norms, grid 512 (one warp per row)
// ============================================================================
__global__ void k_nrt(const float* __restrict__ Rr)
{
    int blk = blockIdx.x;
    int b = blk >> 4, r = (blk & 15)*8 + (threadIdx.x >> 5);
    int lane = threadIdx.x & 31;
    const float* row = Rr + (size_t)(b*LR + r) * D;
    float s = 0.f;
    #pragma unroll 4
    for (int i = lane; i < D; i += 32){ float v = row[i]; s = fmaf(v, v, s); }
    #pragma unroll
    for (int off = 16; off; off >>= 1) s += __shfl_xor_sync(0xffffffffu, s, off);
    if (!lane) g_invnrt[b*LR + r] = rsqrtf(fmaxf(s, 1e-6f));
}

// ============================================================================
// k_idx: argmax_r cosine(L[l], R[r]).  block = 32 l x 128 r, grid (4, B).
// ============================================================================
__global__ void __launch_bounds__(256) k_idx(
    const float* __restrict__ Lr, const float* __restrict__ Rr)
{
    __shared__ float Ls[16*36];
    __shared__ float Rs[16*132];
    __shared__ float sn[128];
    __shared__ float redv[32*17];
    __shared__ int   redi[32*17];

    int b = blockIdx.y, l0 = blockIdx.x*32, t = threadIdx.x;
    if (t < 128) sn[t] = g_invnrt[b*LR + t];

    int ly = t >> 4, tx = t & 15;
    float acc[2][8];
    #pragma unroll
    for (int i = 0; i < 2; i++)
        #pragma unroll
        for (int j = 0; j < 8; j++) acc[i][j] = 0.f;

    const float* Lb = Lr + (size_t)(b*LL + l0) * D;
    const float* Rb = Rr + ((size_t)b << 16);

    for (int kc = 0; kc < 32; kc++){
        __syncthreads();
        {
            int row = t >> 3, c2 = (t & 7)*2;
            float2 v = *(const float2*)(Lb + (size_t)row*D + kc*16 + c2);
            Ls[c2*36 + row] = v.x;
            Ls[(c2+1)*36 + row] = v.y;
        }
        {
            int row = t >> 1, c8 = (t & 1)*8;
            const float* src = Rb + (size_t)row*D + kc*16 + c8;
            float4 v0 = *(const float4*)src, v1 = *(const float4*)(src + 4);
            Rs[(c8+0)*132 + row] = v0.x; Rs[(c8+1)*132 + row] = v0.y;
            Rs[(c8+2)*132 + row] = v0.z; Rs[(c8+3)*132 + row] = v0.w;
            Rs[(c8+4)*132 + row] = v1.x; Rs[(c8+5)*132 + row] = v1.y;
            Rs[(c8+6)*132 + row] = v1.z; Rs[(c8+7)*132 + row] = v1.w;
        }
        __syncthreads();
        #pragma unroll
        for (int k = 0; k < 16; k++){
            float a0 = Ls[k*36 + ly], a1 = Ls[k*36 + ly + 16];
            float4 b0 = *(const float4*)&Rs[k*132 + tx*8];
            float4 b1 = *(const float4*)&Rs[k*132 + tx*8 + 4];
            float bv[8] = {b0.x,b0.y,b0.z,b0.w,b1.x,b1.y,b1.z,b1.w};
            #pragma unroll
            for (int j = 0; j < 8; j++){
                acc[0][j] = fmaf(a0, bv[j], acc[0][j]);
                acc[1][j] = fmaf(a1, bv[j], acc[1][j]);
            }
        }
    }
    #pragma unroll
    for (int i = 0; i < 2; i++){
        float bv = -1e30f; int bi = 0;
        #pragma unroll
        for (int j = 0; j < 8; j++){
            float v = acc[i][j] * sn[tx*8 + j];
            if (v > bv){ bv = v; bi = tx*8 + j; }
        }
        redv[(ly + i*16)*17 + tx] = bv;
        redi[(ly + i*16)*17 + tx] = bi;
    }
    __syncthreads();
    if (t < 32){
        float bv = -1e30f; int bi = 0;
        #pragma unroll
        for (int j = 0; j < 16; j++){
            float v = redv[t*17 + j];
            if (v > bv){ bv = v; bi = redi[t*17 + j]; }
        }
        g_idx[b*LL + l0 + t] = bi;
    }
}

// ============================================================================
// k_mp3: one mp_match epilogue (mode per launch).  grid 256.
// ============================================================================
__global__ void __launch_bounds__(256) k_mp3(
    const float* __restrict__ Lr, const float* __restrict__ hfw,
    const float* __restrict__ hbw, const float* __restrict__ Kmat,
    const float* __restrict__ Rr, float* __restrict__ out,
    int mode, int col0)
{
    __shared__ __align__(16) float P[16][68];
    __shared__ __align__(16) float Kc[64][68];
    __shared__ float hv[512];
    __shared__ float red[16][65];
    __shared__ int   sidx[16];

    int blk = blockIdx.x;
    int b = blk >> 3, l0 = (blk & 7) * 16;
    int t = threadIdx.x;

    if (mode == 0) { hv[t] = hfw[b*256 + t]; hv[256 + t] = hbw[b*256 + t]; }
    if (mode == 2 && t < 16) sidx[t] = g_idx[b*LL + l0 + t];

    int li = t >> 4, mj = t & 15;
    int srow = t >> 6, sk = t & 63;
    float cacc[4] = {0.f, 0.f, 0.f, 0.f};
    float acc[4]  = {0.f, 0.f, 0.f, 0.f};
    __syncthreads();

    for (int c = 0; c < 8; c++) {
        #pragma unroll
        for (int i = 0; i < 16; i++) {
            int f = i * 256 + t; int m = f >> 6, k = f & 63;
            Kc[m][k] = Kmat[(size_t)m * D + c*64 + k];
        }
        #pragma unroll
        for (int i = 0; i < 4; i++) {
            int row = i*4 + srow;
            int gl = b*LL + l0 + row;
            float lv = Lr[(size_t)gl * D + c*64 + sk];
            float av;
            if (mode == 0)      av = hv[c*64 + sk];
            else if (mode == 1) av = g_att[(size_t)gl * D + c*64 + sk];
            else                av = Rr[(size_t)(b*LR + sidx[row]) * D + c*64 + sk];
            float p = lv * av;
            P[row][sk] = p;
            cacc[i] += p;
        }
        __syncthreads();
        #pragma unroll
        for (int k4 = 0; k4 < 16; k4++) {
            float4 p4 = *(const float4*)&P[li][k4*4];
            #pragma unroll
            for (int j = 0; j < 4; j++) {
                float4 kv = *(const float4*)&Kc[j*16 + mj][k4*4];
                acc[j] = fmaf(p4.x, kv.x, fmaf(p4.y, kv.y, fmaf(p4.z, kv.z, fmaf(p4.w, kv.w, acc[j]))));
            }
        }
        __syncthreads();
    }
    #pragma unroll
    for (int i = 0; i < 4; i++) red[i*4 + srow][sk] = cacc[i];
    __syncthreads();
    if (t < 16) {
        float s = 0.f;
        #pragma unroll
        for (int k = 0; k < 64; k++) s += red[t][k];
        out[(size_t)(b*LL + l0 + t) * OC + col0] = tanhf(s);
    }
    #pragma unroll
    for (int j = 0; j < 4; j++)
        out[(size_t)(b*LL + l0 + li) * OC + col0 + 1 + j*16 + mj] = tanhf(acc[j]);
}

// ============================================================================
extern "C" void kernel_launch(void* const* d_in, const int* in_sizes, int n_in,
                              void* d_out, int out_size)
{
    const float* reps_lt = (const float*)d_in[0];
    const float* reps_rt = (const float*)d_in[3];
    const float* h_rt_fw = (const float*)d_in[4];
    const float* h_rt_bw = (const float*)d_in[5];
    const float* k_full  = (const float*)d_in[6];
    const float* k_mpW   = (const float*)d_in[7];
    const float* attn_w1 = (const float*)d_in[8];
    const float* diag_w  = (const float*)d_in[9];
    const float* k_attW  = (const float*)d_in[10];
    const float* k_maxW  = (const float*)d_in[11];
    float* out = (float*)d_out;

    static cudaStream_t s2 = 0, s3 = 0;
    static cudaEvent_t  eF = 0, eJ2 = 0, eJ3 = 0;
    if (!s2) {
        cudaFuncSetAttribute(k_mpool_mma, cudaFuncAttributeMaxDynamicSharedMemorySize, 100352);
        cudaFuncSetAttribute(k_algt_mma,  cudaFuncAttributeMaxDynamicSharedMemorySize, 131072);
        cudaStreamCreateWithFlags(&s2, cudaStreamNonBlocking);
        cudaStreamCreateWithFlags(&s3, cudaStreamNonBlocking);
        cudaEventCreateWithFlags(&eF,  cudaEventDisableTiming);
        cudaEventCreateWithFlags(&eJ2, cudaEventDisableTiming);
        cudaEventCreateWithFlags(&eJ3, cudaEventDisableTiming);
    }

    // main: split L first (needed by mpool AND algt_mma), then fork
    k_split<<<dim3(8, B), 256>>>(reps_lt, 0);
    cudaEventRecord(eF, 0);
    cudaStreamWaitEvent(s2, eF, 0);
    cudaStreamWaitEvent(s3, eF, 0);

    // main stream: dominant tensor-core chain (cols 65..128)
    k_mpool_mma<<<dim3(64, B), 256, 100352>>>(reps_rt, k_mpW, out);

    // s2: attentive path -> mp3 mode1 (cols 129..193)
    k_split<<<dim3(8, B), 256, 0, s2>>>(reps_rt, 1);
    k_splitW<<<dim3(8, 8), 256, 0, s2>>>(attn_w1);
    k_algt_mma<<<64, 256, 131072, s2>>>(diag_w);
    k_score<<<dim3(4, B), 256, 0, s2>>>();
    k_pr<<<dim3(32, B), 256, 0, s2>>>(reps_rt);
    k_mp3<<<256, 256, 0, s2>>>(reps_lt, h_rt_fw, h_rt_bw, k_attW, reps_rt, out, 1, 129);

    // s3: full match (cols 0..64) + max-attentive -> mp3 mode2 (cols 194..258)
    k_mp3<<<256, 256, 0, s3>>>(reps_lt, h_rt_fw, h_rt_bw, k_full, reps_rt, out, 0, 0);
    k_nrt<<<512, 256, 0, s3>>>(reps_rt);
    k_idx<<<dim3(4, B), 256, 0, s3>>>(reps_lt, reps_rt);
    k_mp3<<<256, 256, 0, s3>>>(reps_lt, h_rt_fw, h_rt_bw, k_maxW, reps_rt, out, 2, 194);

    // join side streams back into the main stream
    cudaEventRecord(eJ2, s2);
    cudaEventRecord(eJ3, s3);
    cudaStreamWaitEvent(0, eJ2, 0);
    cudaStreamWaitEvent(0, eJ3, 0);
}

// round 14
// speedup vs baseline: 1.2944x; 1.1302x over previous
#include <cuda_runtime.h>
#include <math.h>
#include <stdint.h>

#define B   32
#define LL  128
#define LR  128
#define D   512
#define A   128
#define OC  259   // 1+64 | 64 | 1+64 | 1+64

// ---- scratch (static device globals; no runtime allocation) ----
__device__ float g_algt[(B*LL + B*LR) * A];
__device__ float g_att[B*LL*D];
__device__ float g_invnrt[B*LR];
__device__ int   g_idx[B*LL];
// pre-split bf16 hi/lo swizzled tiles: (b,chunk) tiles of 128 rows x 128B
__device__ __align__(16) unsigned char g_Lh[B*8*16384];
__device__ __align__(16) unsigned char g_Ll[B*8*16384];
__device__ __align__(16) unsigned char g_Rh[B*8*16384];
__device__ __align__(16) unsigned char g_Rl[B*8*16384];
// W1 transposed to B-operand tiles: 8 chunks x (128 a-rows x 64 d) hi/lo
__device__ __align__(16) unsigned char g_Wh[8*16384];
__device__ __align__(16) unsigned char g_Wl[8*16384];
// softmax probs as A-operand tiles: (b, r-chunk) of 128 l-rows x 64 r
__device__ __align__(16) unsigned char g_Ph[B*2*16384];
__device__ __align__(16) unsigned char g_Pl[B*2*16384];
// R transposed to B-operand tiles: (b, nt*2+rc): 128 d-rows x 64 r
__device__ __align__(16) unsigned char g_RTh[B*8*16384];
__device__ __align__(16) unsigned char g_RTl[B*8*16384];

__device__ __forceinline__ uint32_t swz(uint32_t x){ return x ^ ((x >> 3) & 0x70u); }
__device__ __forceinline__ uint32_t smem_u32(const void* p){
    uint32_t a;
    asm("{ .reg .u64 t; cvta.to.shared.u64 t, %1; cvt.u32.u64 %0, t; }" : "=r"(a) : "l"(p));
    return a;
}
__device__ __forceinline__ void split2(float x0, float x1, uint32_t& h, uint32_t& l){
    asm("cvt.rn.bf16x2.f32 %0, %1, %2;" : "=r"(h) : "f"(x1), "f"(x0));
    float h0 = __uint_as_float(h << 16), h1 = __uint_as_float(h & 0xffff0000u);
    asm("cvt.rn.bf16x2.f32 %0, %1, %2;" : "=r"(l) : "f"(x1 - h1), "f"(x0 - h0));
}

#define LDSM4(r0,r1,r2,r3,addr) \
    asm volatile("ldmatrix.sync.aligned.m8n8.x4.shared.b16 {%0,%1,%2,%3}, [%4];" \
        : "=r"(r0),"=r"(r1),"=r"(r2),"=r"(r3) : "r"(addr))
#define CP16(s,g) \
    asm volatile("cp.async.cg.shared.global [%0], [%1], 16;" :: "r"(s), "l"(g))
#define CPCOMMIT() asm volatile("cp.async.commit_group;")
#define CPWAIT1()  asm volatile("cp.async.wait_group 1;")
#define CPWAIT0()  asm volatile("cp.async.wait_group 0;")

__device__ __forceinline__ void mma_bf16(float* d, const uint32_t* a, const uint32_t* b){
    asm volatile("mma.sync.aligned.m16n8k16.row.col.f32.bf16.bf16.f32 "
        "{%0,%1,%2,%3}, {%4,%5,%6,%7}, {%8,%9}, {%0,%1,%2,%3};"
        : "+f"(d[0]),"+f"(d[1]),"+f"(d[2]),"+f"(d[3])
        : "r"(a[0]),"r"(a[1]),"r"(a[2]),"r"(a[3]), "r"(b[0]),"r"(b[1]));
}

// ============================================================================
// k_split: X (fp32) -> hi/lo bf16 swizzled tiles. grid (8, B). which: 0=L 1=R
// ============================================================================
__global__ void __launch_bounds__(256) k_split(const float* __restrict__ X, int which)
{
    int c = blockIdx.x, b = blockIdx.y, t = threadIdx.x;
    const float* Xb = X + ((size_t)b << 16) + c*64;
    size_t tile = ((size_t)(b*8 + c)) << 14;
    unsigned char* dh = (which ? g_Rh : g_Lh) + tile;
    unsigned char* dl = (which ? g_Rl : g_Ll) + tile;
    #pragma unroll
    for (int i = 0; i < 4; i++){
        int f = i*256 + t; int row = f >> 3, q = f & 7;
        const float* src = Xb + (size_t)row*512 + q*8;
        float4 v0 = *(const float4*)src, v1 = *(const float4*)(src + 4);
        uint32_t h01,l01,h23,l23,h45,l45,h67,l67;
        split2(v0.x, v0.y, h01, l01);
        split2(v0.z, v0.w, h23, l23);
        split2(v1.x, v1.y, h45, l45);
        split2(v1.z, v1.w, h67, l67);
        uint32_t off = swz((uint32_t)(row*128 + q*16));
        *(uint4*)(dh + off) = make_uint4(h01, h23, h45, h67);
        *(uint4*)(dl + off) = make_uint4(l01, l23, l45, l67);
    }
}

// ============================================================================
// k_splitW: W1 [d=512][a=128] -> transposed B tiles. grid (8, 8).
// ============================================================================
__global__ void __launch_bounds__(256) k_splitW(const float* __restrict__ W1)
{
    int c = blockIdx.x, t = threadIdx.x;
    size_t tile = ((size_t)c) << 14;
    int i = blockIdx.y;
    {
        int f = i*256 + t; int row = f >> 4, q = f & 15;
        int d0 = c*64 + q*4;
        float w0 = W1[(size_t)(d0+0)*A + row];
        float w1 = W1[(size_t)(d0+1)*A + row];
        float w2 = W1[(size_t)(d0+2)*A + row];
        float w3 = W1[(size_t)(d0+3)*A + row];
        uint32_t h01,l01,h23,l23;
        split2(w0, w1, h01, l01);
        split2(w2, w3, h23, l23);
        uint32_t off = swz((uint32_t)(row*128 + q*8));
        *(uint2*)(g_Wh + tile + off) = make_uint2(h01, h23);
        *(uint2*)(g_Wl + tile + off) = make_uint2(l01, l23);
    }
}

// ============================================================================
// k_splitRT: R -> transposed B tiles (rows=d, k=r). grid (8, B); j = nt*2+rc.
// tile (b, j): d in [128*(j>>1), +128), r in [64*(j&1), +64).
// Rsm stride 132 floats (528 B, 16B-aligned for float4 row writes).
// ============================================================================
__global__ void __launch_bounds__(256) k_splitRT(const float* __restrict__ Rr)
{
    __shared__ __align__(16) float Rsm[64*132];
    int j = blockIdx.x, b = blockIdx.y, t = threadIdx.x;
    int nt = j >> 1, rc = j & 1;
    const float* src = Rr + ((size_t)b << 16) + (size_t)(rc*64)*512 + nt*128;
    #pragma unroll
    for (int i = 0; i < 8; i++){
        int f = i*256 + t; int row = f >> 5, dc = (f & 31)*4;
        *(float4*)&Rsm[row*132 + dc] = *(const float4*)(src + (size_t)row*512 + dc);
    }
    __syncthreads();
    size_t tile = ((size_t)(b*8 + j)) << 14;
    #pragma unroll
    for (int i = 0; i < 4; i++){
        int f = i*256 + t; int drow = f >> 3, oct = f & 7;
        int r0 = oct*8;
        float v[8];
        #pragma unroll
        for (int k = 0; k < 8; k++) v[k] = Rsm[(r0+k)*132 + drow];
        uint32_t h01,l01,h23,l23,h45,l45,h67,l67;
        split2(v[0],v[1],h01,l01); split2(v[2],v[3],h23,l23);
        split2(v[4],v[5],h45,l45); split2(v[6],v[7],h67,l67);
        uint32_t off = swz((uint32_t)(drow*128 + oct*16));
        *(uint4*)(g_RTh + tile + off) = make_uint4(h01,h23,h45,h67);
        *(uint4*)(g_RTl + tile + off) = make_uint4(l01,l23,l45,l67);
    }
}

// ============================================================================
// k_mpool_mma: CTA = (m, b).  C[l,r] = sum_d L[l,d]*(R[r,d]*K_m[d]).
// out[b,l,65+m] = tanh(max_r C).  dyn smem 100352 B, occ 2.
// ============================================================================
__global__ void __launch_bounds__(256, 2) k_mpool_mma(
    const float* __restrict__ Rr, const float* __restrict__ Kmp,
    float* __restrict__ out)
{
    extern __shared__ __align__(16) unsigned char dyn[];
    int m = blockIdx.x, b = blockIdx.y;
    int t = threadIdx.x, wid = t >> 5, lane = t & 31;
    uint32_t base = smem_u32(dyn);
    uint32_t Abuf[2] = {base, base + 32768};
    uint32_t Bh = base + 65536, Bl = base + 81920;
    float* sK = (float*)(dyn + 98304);
    for (int i = t; i < 512; i += 256) sK[i] = Kmp[(size_t)m*512 + i];

    {
        const unsigned char* gh = g_Lh + (((size_t)(b*8)) << 14);
        const unsigned char* gl = g_Ll + (((size_t)(b*8)) << 14);
        #pragma unroll
        for (int i = 0; i < 4; i++){
            uint32_t o = (uint32_t)(i*256 + t) * 16;
            CP16(Abuf[0] + o, gh + o);
            CP16(Abuf[0] + 16384 + o, gl + o);
        }
        CPCOMMIT();
    }
    __syncthreads();

    int wl = wid >> 2, wn = wid & 3;
    float acc[4][4][4];
    #pragma unroll
    for (int i = 0; i < 4; i++)
        #pragma unroll
        for (int j = 0; j < 4; j++)
            #pragma unroll
            for (int k = 0; k < 4; k++) acc[i][j][k] = 0.f;

    int rowA = lane & 15;
    int cbA  = lane >> 4;
    int rowB = ((lane >> 4) & 1) * 8 + (lane & 7);
    int cbB  = (lane >> 3) & 1;

    const float* Rb = Rr + ((size_t)b << 16);
    int rrow = t >> 3, rq = t & 7;

    for (int c = 0; c < 8; c++){
        if (c < 7){
            uint32_t nb = Abuf[(c+1) & 1];
            const unsigned char* gh = g_Lh + (((size_t)(b*8 + c+1)) << 14);
            const unsigned char* gl = g_Ll + (((size_t)(b*8 + c+1)) << 14);
            #pragma unroll
            for (int i = 0; i < 4; i++){
                uint32_t o = (uint32_t)(i*256 + t) * 16;
                CP16(nb + o, gh + o);
                CP16(nb + 16384 + o, gl + o);
            }
            CPCOMMIT();
        }
        {
            float4 k0 = *(const float4*)(sK + c*64 + rq*8);
            float4 k1 = *(const float4*)(sK + c*64 + rq*8 + 4);
            #pragma unroll
            for (int i = 0; i < 4; i++){
                int row = rrow + i*32;
                const float* src = Rb + (size_t)row*512 + c*64 + rq*8;
                float4 r0 = *(const float4*)src, r1 = *(const float4*)(src + 4);
                uint32_t h01,l01,h23,l23,h45,l45,h67,l67;
                split2(r0.x*k0.x, r0.y*k0.y, h01, l01);
                split2(r0.z*k0.z, r0.w*k0.w, h23, l23);
                split2(r1.x*k1.x, r1.y*k1.y, h45, l45);
                split2(r1.z*k1.z, r1.w*k1.w, h67, l67);
                uint32_t off = swz((uint32_t)(row*128 + rq*16));
                asm volatile("st.shared.v4.b32 [%0], {%1,%2,%3,%4};"
                             :: "r"(Bh+off), "r"(h01), "r"(h23), "r"(h45), "r"(h67));
                asm volatile("st.shared.v4.b32 [%0], {%1,%2,%3,%4};"
                             :: "r"(Bl+off), "r"(l01), "r"(l23), "r"(l45), "r"(l67));
            }
        }
        if (c < 7) { CPWAIT1(); } else { CPWAIT0(); }
        __syncthreads();

        uint32_t Ah = Abuf[c & 1], Al = Ah + 16384;
        #pragma unroll
        for (int ks = 0; ks < 4; ks++){
            uint32_t aoffs[4], boffs[2];
            #pragma unroll
            for (int mt = 0; mt < 4; mt++)
                aoffs[mt] = swz((uint32_t)((wl*64 + mt*16 + rowA)*128 + ks*32 + cbA*16));
            #pragma unroll
            for (int jp = 0; jp < 2; jp++)
                boffs[jp] = swz((uint32_t)((wn*32 + jp*16 + rowB)*128 + ks*32 + cbB*16));

            uint32_t bh_[4][2];
            #pragma unroll
            for (int jp = 0; jp < 2; jp++)
                LDSM4(bh_[jp*2][0], bh_[jp*2][1], bh_[jp*2+1][0], bh_[jp*2+1][1], Bh + boffs[jp]);
            {
                uint32_t al_[4][4];
                #pragma unroll
                for (int mt = 0; mt < 4; mt++)
                    LDSM4(al_[mt][0], al_[mt][1], al_[mt][2], al_[mt][3], Al + aoffs[mt]);
                #pragma unroll
                for (int mt = 0; mt < 4; mt++)
                    #pragma unroll
                    for (int nt = 0; nt < 4; nt++)
                        mma_bf16(acc[mt][nt], al_[mt], bh_[nt]);
            }
            uint32_t ah_[4][4];
            #pragma unroll
            for (int mt = 0; mt < 4; mt++)
                LDSM4(ah_[mt][0], ah_[mt][1], ah_[mt][2], ah_[mt][3], Ah + aoffs[mt]);
            #pragma unroll
            for (int mt = 0; mt < 4; mt++)
                #pragma unroll
                for (int nt = 0; nt < 4; nt++)
                    mma_bf16(acc[mt][nt], ah_[mt], bh_[nt]);
            {
                uint32_t bl_[4][2];
                #pragma unroll
                for (int jp = 0; jp < 2; jp++)
                    LDSM4(bl_[jp*2][0], bl_[jp*2][1], bl_[jp*2+1][0], bl_[jp*2+1][1], Bl + boffs[jp]);
                #pragma unroll
                for (int mt = 0; mt < 4; mt++)
                    #pragma unroll
                    for (int nt = 0; nt < 4; nt++)
                        mma_bf16(acc[mt][nt], ah_[mt], bl_[nt]);
            }
        }
        __syncthreads();
    }

    float* red = (float*)dyn;
    int g = lane >> 2, tg = lane & 3;
    #pragma unroll
    for (int mt = 0; mt < 4; mt++){
        float m0 = -1e30f, m1 = -1e30f;
        #pragma unroll
        for (int nt = 0; nt < 4; nt++){
            m0 = fmaxf(m0, fmaxf(acc[mt][nt][0], acc[mt][nt][1]));
            m1 = fmaxf(m1, fmaxf(acc[mt][nt][2], acc[mt][nt][3]));
        }
        m0 = fmaxf(m0, __shfl_xor_sync(0xffffffffu, m0, 1));
        m0 = fmaxf(m0, __shfl_xor_sync(0xffffffffu, m0, 2));
        m1 = fmaxf(m1, __shfl_xor_sync(0xffffffffu, m1, 1));
        m1 = fmaxf(m1, __shfl_xor_sync(0xffffffffu, m1, 2));
        if (tg == 0){
            red[(wl*64 + mt*16 + g)*4 + wn]     = m0;
            red[(wl*64 + mt*16 + g + 8)*4 + wn] = m1;
        }
    }
    __syncthreads();
    if (t < 128){
        float v = fmaxf(fmaxf(red[t*4], red[t*4+1]), fmaxf(red[t*4+2], red[t*4+3]));
        out[((size_t)(b*LL + t))*OC + 65 + m] = tanhf(v);
    }
}

// ============================================================================
// k_algt_mma: tanh([L;R] @ W1) (*diag for L rows).  grid 64, dbl-buf 131072 B.
// ============================================================================
__global__ void __launch_bounds__(256) k_algt_mma(const float* __restrict__ diag)
{
    extern __shared__ __align__(16) unsigned char dyn[];
    __shared__ float sdiag[128];
    int bi = blockIdx.x;
    int isL = (bi < 32) ? 1 : 0;
    int b = isL ? bi : bi - 32;
    int t = threadIdx.x, wid = t >> 5, lane = t & 31;
    uint32_t base = smem_u32(dyn);
    uint32_t buf[2] = {base, base + 65536};

    if (t < 128) sdiag[t] = diag[t];

    const unsigned char* srcH = isL ? g_Lh : g_Rh;
    const unsigned char* srcL = isL ? g_Ll : g_Rl;

    {
        const unsigned char* ah = srcH + (((size_t)(b*8)) << 14);
        const unsigned char* al = srcL + (((size_t)(b*8)) << 14);
        #pragma unroll
        for (int i = 0; i < 4; i++){
            uint32_t o = (uint32_t)(i*256 + t) * 16;
            CP16(buf[0] + o,         ah + o);
            CP16(buf[0] + 16384 + o, al + o);
            CP16(buf[0] + 32768 + o, g_Wh + o);
            CP16(buf[0] + 49152 + o, g_Wl + o);
        }
        CPCOMMIT();
    }

    int wl = wid >> 2, wn = wid & 3;
    float acc[4][4][4];
    #pragma unroll
    for (int i = 0; i < 4; i++)
        #pragma unroll
        for (int j = 0; j < 4; j++)
            #pragma unroll
            for (int k = 0; k < 4; k++) acc[i][j][k] = 0.f;

    int rowA = lane & 15;
    int cbA  = lane >> 4;
    int rowB = ((lane >> 4) & 1) * 8 + (lane & 7);
    int cbB  = (lane >> 3) & 1;

    for (int c = 0; c < 8; c++){
        if (c < 7){
            uint32_t nb = buf[(c+1) & 1];
            const unsigned char* ah = srcH + (((size_t)(b*8 + c+1)) << 14);
            const unsigned char* al = srcL + (((size_t)(b*8 + c+1)) << 14);
            const unsigned char* wh = g_Wh + (((size_t)(c+1)) << 14);
            const unsigned char* wlp = g_Wl + (((size_t)(c+1)) << 14);
            #pragma unroll
            for (int i = 0; i < 4; i++){
                uint32_t o = (uint32_t)(i*256 + t) * 16;
                CP16(nb + o,         ah + o);
                CP16(nb + 16384 + o, al + o);
                CP16(nb + 32768 + o, wh + o);
                CP16(nb + 49152 + o, wlp + o);
            }
            CPCOMMIT();
        }
        if (c < 7) { CPWAIT1(); } else { CPWAIT0(); }
        __syncthreads();

        uint32_t Ah = buf[c & 1], Al = Ah + 16384, Wh = Ah + 32768, Wlb = Ah + 49152;
        #pragma unroll
        for (int ks = 0; ks < 4; ks++){
            uint32_t aoffs[4], boffs[2];
            #pragma unroll
            for (int mt = 0; mt < 4; mt++)
                aoffs[mt] = swz((uint32_t)((wl*64 + mt*16 + rowA)*128 + ks*32 + cbA*16));
            #pragma unroll
            for (int jp = 0; jp < 2; jp++)
                boffs[jp] = swz((uint32_t)((wn*32 + jp*16 + rowB)*128 + ks*32 + cbB*16));

            uint32_t bh_[4][2];
            #pragma unroll
            for (int jp = 0; jp < 2; jp++)
                LDSM4(bh_[jp*2][0], bh_[jp*2][1], bh_[jp*2+1][0], bh_[jp*2+1][1], Wh + boffs[jp]);
            {
                uint32_t al_[4][4];
                #pragma unroll
                for (int mt = 0; mt < 4; mt++)
                    LDSM4(al_[mt][0], al_[mt][1], al_[mt][2], al_[mt][3], Al + aoffs[mt]);
                #pragma unroll
                for (int mt = 0; mt < 4; mt++)
                    #pragma unroll
                    for (int nt = 0; nt < 4; nt++)
                        mma_bf16(acc[mt][nt], al_[mt], bh_[nt]);
            }
            uint32_t ah_[4][4];
            #pragma unroll
            for (int mt = 0; mt < 4; mt++)
                LDSM4(ah_[mt][0], ah_[mt][1], ah_[mt][2], ah_[mt][3], Ah + aoffs[mt]);
            #pragma unroll
            for (int mt = 0; mt < 4; mt++)
                #pragma unroll
                for (int nt = 0; nt < 4; nt++)
                    mma_bf16(acc[mt][nt], ah_[mt], bh_[nt]);
            {
                uint32_t bl_[4][2];
                #pragma unroll
                for (int jp = 0; jp < 2; jp++)
                    LDSM4(bl_[jp*2][0], bl_[jp*2][1], bl_[jp*2+1][0], bl_[jp*2+1][1], Wlb + boffs[jp]);
                #pragma unroll
                for (int mt = 0; mt < 4; mt++)
                    #pragma unroll
                    for (int nt = 0; nt < 4; nt++)
                        mma_bf16(acc[mt][nt], ah_[mt], bl_[nt]);
            }
        }
        __syncthreads();
    }

    int g = lane >> 2, tg = lane & 3;
    size_t rbase = (size_t)bi * 128;
    #pragma unroll
    for (int mt = 0; mt < 4; mt++){
        int r0 = wl*64 + mt*16 + g, r1 = r0 + 8;
        #pragma unroll
        for (int nt = 0; nt < 4; nt++){
            int col = wn*32 + nt*8 + tg*2;
            float d0 = isL ? sdiag[col] : 1.f;
            float d1 = isL ? sdiag[col+1] : 1.f;
            float2 v0 = make_float2(tanhf(acc[mt][nt][0])*d0, tanhf(acc[mt][nt][1])*d1);
            float2 v1 = make_float2(tanhf(acc[mt][nt][2])*d0, tanhf(acc[mt][nt][3])*d1);
            *(float2*)&g_algt[(rbase + r0)*A + col] = v0;
            *(float2*)&g_algt[(rbase + r1)*A + col] = v1;
        }
    }
}

// ============================================================================
// k_score: register-tiled scores + softmax -> bf16 hi/lo P-tiles (g_Ph/g_Pl).
// grid (4, B): 32 l x 128 r.
// ============================================================================
__global__ void __launch_bounds__(256) k_score()
{
    __shared__ float Ls[16*36];
    __shared__ float Rs[16*132];
    __shared__ __align__(16) float S[32*132];

    int b = blockIdx.y, l0 = blockIdx.x*32, t = threadIdx.x;
    int ly = t >> 4, tx = t & 15;
    float acc[2][8];
    #pragma unroll
    for (int i = 0; i < 2; i++)
        #pragma unroll
        for (int j = 0; j < 8; j++) acc[i][j] = 0.f;

    const float* Lb = g_algt + (size_t)(b*LL + l0) * A;
    const float* Rb = g_algt + (size_t)(B*LL + b*LR) * A;

    for (int kc = 0; kc < 8; kc++){
        __syncthreads();
        {
            int row = t >> 3, c2 = (t & 7)*2;
            float2 v = *(const float2*)(Lb + (size_t)row*A + kc*16 + c2);
            Ls[c2*36 + row] = v.x;
            Ls[(c2+1)*36 + row] = v.y;
        }
        {
            int row = t >> 1, c8 = (t & 1)*8;
            const float* src = Rb + (size_t)row*A + kc*16 + c8;
            float4 v0 = *(const float4*)src, v1 = *(const float4*)(src + 4);
            Rs[(c8+0)*132 + row] = v0.x; Rs[(c8+1)*132 + row] = v0.y;
            Rs[(c8+2)*132 + row] = v0.z; Rs[(c8+3)*132 + row] = v0.w;
            Rs[(c8+4)*132 + row] = v1.x; Rs[(c8+5)*132 + row] = v1.y;
            Rs[(c8+6)*132 + row] = v1.z; Rs[(c8+7)*132 + row] = v1.w;
        }
        __syncthreads();
        #pragma unroll
        for (int k = 0; k < 16; k++){
            float a0 = Ls[k*36 + ly], a1 = Ls[k*36 + ly + 16];
            float4 b0 = *(const float4*)&Rs[k*132 + tx*8];
            float4 b1 = *(const float4*)&Rs[k*132 + tx*8 + 4];
            float bv[8] = {b0.x,b0.y,b0.z,b0.w,b1.x,b1.y,b1.z,b1.w};
            #pragma unroll
            for (int j = 0; j < 8; j++){
                acc[0][j] = fmaf(a0, bv[j], acc[0][j]);
                acc[1][j] = fmaf(a1, bv[j], acc[1][j]);
            }
        }
    }
    #pragma unroll
    for (int i = 0; i < 2; i++)
        #pragma unroll
        for (int j = 0; j < 8; j++)
            S[(ly + i*16)*132 + tx*8 + j] = acc[i][j];
    __syncthreads();

    // softmax: warp w -> rows 4w..4w+3, write probs back to S
    int w = t >> 5, lane = t & 31;
    #pragma unroll
    for (int rr = w*4; rr < w*4 + 4; rr++){
        float v0 = S[rr*132+lane], v1 = S[rr*132+lane+32],
              v2 = S[rr*132+lane+64], v3 = S[rr*132+lane+96];
        float m0 = fmaxf(fmaxf(v0,v1), fmaxf(v2,v3));
        #pragma unroll
        for (int off = 16; off; off >>= 1) m0 = fmaxf(m0, __shfl_xor_sync(0xffffffffu, m0, off));
        float e0 = expf(v0-m0), e1 = expf(v1-m0), e2 = expf(v2-m0), e3 = expf(v3-m0);
        float sum = e0+e1+e2+e3;
        #pragma unroll
        for (int off = 16; off; off >>= 1) sum += __shfl_xor_sync(0xffffffffu, sum, off);
        float inv = 1.f / sum;
        S[rr*132+lane] = e0*inv; S[rr*132+lane+32] = e1*inv;
        S[rr*132+lane+64] = e2*inv; S[rr*132+lane+96] = e3*inv;
    }
    __syncthreads();

    // write P tiles (bf16 hi/lo, swizzled A-operand layout)
    #pragma unroll
    for (int it = 0; it < 2; it++){
        int f = it*256 + t;
        int row = f >> 4, oct = f & 15;
        int c = oct >> 3;
        const float* sp = &S[row*132 + oct*8];
        float4 p0 = *(const float4*)sp, p1 = *(const float4*)(sp + 4);
        uint32_t h01,l01,h23,l23,h45,l45,h67,l67;
        split2(p0.x,p0.y,h01,l01); split2(p0.z,p0.w,h23,l23);
        split2(p1.x,p1.y,h45,l45); split2(p1.z,p1.w,h67,l67);
        int l = l0 + row;
        uint32_t off = swz((uint32_t)(l*128 + (oct & 7)*16));
        size_t tile = ((size_t)(b*2 + c)) << 14;
        *(uint4*)(g_Ph + tile + off) = make_uint4(h01,h23,h45,h67);
        *(uint4*)(g_Pl + tile + off) = make_uint4(l01,l23,l45,l67);
    }
}

// ============================================================================
// k_pr_mma: att = P @ R via 3-term split bf16 MMA.  grid (4 d-tiles, B).
// A = P tiles (g_Ph/g_Pl), B = R^T tiles (g_RTh/g_RTl).  K=128 (2 chunks).
// dyn smem 131072: Ph@0 (2 ch) | Pl@32K | Bh@64K | Bl@96K.
// ============================================================================
__global__ void __launch_bounds__(256) k_pr_mma()
{
    extern __shared__ __align__(16) unsigned char dyn[];
    int nt = blockIdx.x, b = blockIdx.y;
    int t = threadIdx.x, wid = t >> 5, lane = t & 31;
    uint32_t base = smem_u32(dyn);

    {
        const unsigned char* ph = g_Ph + (((size_t)(b*2)) << 14);
        const unsigned char* pl = g_Pl + (((size_t)(b*2)) << 14);
        const unsigned char* bh = g_RTh + (((size_t)(b*8 + nt*2)) << 14);
        const unsigned char* bl = g_RTl + (((size_t)(b*8 + nt*2)) << 14);
        #pragma unroll
        for (int i = 0; i < 8; i++){
            uint32_t o = (uint32_t)(i*256 + t) * 16;
            CP16(base + o,          ph + o);
            CP16(base + 32768 + o,  pl + o);
            CP16(base + 65536 + o,  bh + o);
            CP16(base + 98304 + o,  bl + o);
        }
        CPCOMMIT(); CPWAIT0();
    }
    __syncthreads();

    int wl = wid >> 2, wn = wid & 3;
    float acc[4][4][4];
    #pragma unroll
    for (int i = 0; i < 4; i++)
        #pragma unroll
        for (int j = 0; j < 4; j++)
            #pragma unroll
            for (int k = 0; k < 4; k++) acc[i][j][k] = 0.f;

    int rowA = lane & 15;
    int cbA  = lane >> 4;
    int rowB = ((lane >> 4) & 1) * 8 + (lane & 7);
    int cbB  = (lane >> 3) & 1;

    for (int ks8 = 0; ks8 < 8; ks8++){
        int ch = ks8 >> 2, ks = ks8 & 3;
        uint32_t Ah = base + ch*16384,         Al  = base + 32768 + ch*16384;
        uint32_t Bh = base + 65536 + ch*16384, Blb = base + 98304 + ch*16384;
        uint32_t aoffs[4], boffs[2];
        #pragma unroll
        for (int mt = 0; mt < 4; mt++)
            aoffs[mt] = swz((uint32_t)((wl*64 + mt*16 + rowA)*128 + ks*32 + cbA*16));
        #pragma unroll
        for (int jp = 0; jp < 2; jp++)
            boffs[jp] = swz((uint32_t)((wn*32 + jp*16 + rowB)*128 + ks*32 + cbB*16));

        uint32_t bh_[4][2];
        #pragma unroll
        for (int jp = 0; jp < 2; jp++)
            LDSM4(bh_[jp*2][0], bh_[jp*2][1], bh_[jp*2+1][0], bh_[jp*2+1][1], Bh + boffs[jp]);
        {
            uint32_t al_[4][4];
            #pragma unroll
            for (int mt = 0; mt < 4; mt++)
                LDSM4(al_[mt][0], al_[mt][1], al_[mt][2], al_[mt][3], Al + aoffs[mt]);
            #pragma unroll
            for (int mt = 0; mt < 4; mt++)
                #pragma unroll
                for (int n2 = 0; n2 < 4; n2++)
                    mma_bf16(acc[mt][n2], al_[mt], bh_[n2]);
        }
        uint32_t ah_[4][4];
        #pragma unroll
        for (int mt = 0; mt < 4; mt++)
            LDSM4(ah_[mt][0], ah_[mt][1], ah_[mt][2], ah_[mt][3], Ah + aoffs[mt]);
        #pragma unroll
        for (int mt = 0; mt < 4; mt++)
            #pragma unroll
            for (int n2 = 0; n2 < 4; n2++)
                mma_bf16(acc[mt][n2], ah_[mt], bh_[n2]);
        {
            uint32_t bl_[4][2];
            #pragma unroll
            for (int jp = 0; jp < 2; jp++)
                LDSM4(bl_[jp*2][0], bl_[jp*2][1], bl_[jp*2+1][0], bl_[jp*2+1][1], Blb + boffs[jp]);
            #pragma unroll
            for (int mt = 0; mt < 4; mt++)
                #pragma unroll
                for (int n2 = 0; n2 < 4; n2++)
                    mma_bf16(acc[mt][n2], ah_[mt], bl_[n2]);
        }
    }

    // epilogue: write att fp32
    int g = lane >> 2, tg = lane & 3;
    float* ob = g_att + ((size_t)(b*LL))*D + nt*128;
    #pragma unroll
    for (int mt = 0; mt < 4; mt++){
        int r0 = wl*64 + mt*16 + g, r1 = r0 + 8;
        #pragma unroll
        for (int n2 = 0; n2 < 4; n2++){
            int col = wn*32 + n2*8 + tg*2;
            *(float2*)&ob[(size_t)r0*D + col] = make_float2(acc[mt][n2][0], acc[mt][n2][1]);
            *(float2*)&ob[(size_t)r1*D + col] = make_float2(acc[mt][n2][2], acc[mt][n2][3]);
        }
    }
}

// ============================================================================
// k_nrt: inv right norms, grid 512 (one warp per row)
// ============================================================================
__global__ void k_nrt(const float* __restrict__ Rr)
{
    int blk = blockIdx.x;
    int b = blk >> 4, r = (blk & 15)*8 + (threadIdx.x >> 5);
    int lane = threadIdx.x & 31;
    const float* row = Rr + (size_t)(b*LR + r) * D;
    float s = 0.f;
    #pragma unroll 4
    for (int i = lane; i < D; i += 32){ float v = row[i]; s = fmaf(v, v, s); }
    #pragma unroll
    for (int off = 16; off; off >>= 1) s += __shfl_xor_sync(0xffffffffu, s, off);
    if (!lane) g_invnrt[b*LR + r] = rsqrtf(fmaxf(s, 1e-6f));
}

// ============================================================================
// k_idx: argmax_r cosine(L[l], R[r]).  block = 32 l x 128 r, grid (4, B).
// ============================================================================
__global__ void __launch_bounds__(256) k_idx(
    const float* __restrict__ Lr, const float* __restrict__ Rr)
{
    __shared__ float Ls[16*36];
    __shared__ float Rs[16*132];
    __shared__ float sn[128];
    __shared__ float redv[32*17];
    __shared__ int   redi[32*17];

    int b = blockIdx.y, l0 = blockIdx.x*32, t = threadIdx.x;
    if (t < 128) sn[t] = g_invnrt[b*LR + t];

    int ly = t >> 4, tx = t & 15;
    float acc[2][8];
    #pragma unroll
    for (int i = 0; i < 2; i++)
        #pragma unroll
        for (int j = 0; j < 8; j++) acc[i][j] = 0.f;

    const float* Lb = Lr + (size_t)(b*LL + l0) * D;
    const float* Rb = Rr + ((size_t)b << 16);

    for (int kc = 0; kc < 32; kc++){
        __syncthreads();
        {
            int row = t >> 3, c2 = (t & 7)*2;
            float2 v = *(const float2*)(Lb + (size_t)row*D + kc*16 + c2);
            Ls[c2*36 + row] = v.x;
            Ls[(c2+1)*36 + row] = v.y;
        }
        {
            int row = t >> 1, c8 = (t & 1)*8;
            const float* src = Rb + (size_t)row*D + kc*16 + c8;
            float4 v0 = *(const float4*)src, v1 = *(const float4*)(src + 4);
            Rs[(c8+0)*132 + row] = v0.x; Rs[(c8+1)*132 + row] = v0.y;
            Rs[(c8+2)*132 + row] = v0.z; Rs[(c8+3)*132 + row] = v0.w;
            Rs[(c8+4)*132 + row] = v1.x; Rs[(c8+5)*132 + row] = v1.y;
            Rs[(c8+6)*132 + row] = v1.z; Rs[(c8+7)*132 + row] = v1.w;
        }
        __syncthreads();
        #pragma unroll
        for (int k = 0; k < 16; k++){
            float a0 = Ls[k*36 + ly], a1 = Ls[k*36 + ly + 16];
            float4 b0 = *(const float4*)&Rs[k*132 + tx*8];
            float4 b1 = *(const float4*)&Rs[k*132 + tx*8 + 4];
            float bv[8] = {b0.x,b0.y,b0.z,b0.w,b1.x,b1.y,b1.z,b1.w};
            #pragma unroll
            for (int j = 0; j < 8; j++){
                acc[0][j] = fmaf(a0, bv[j], acc[0][j]);
                acc[1][j] = fmaf(a1, bv[j], acc[1][j]);
            }
        }
    }
    #pragma unroll
    for (int i = 0; i < 2; i++){
        float bv = -1e30f; int bi = 0;
        #pragma unroll
        for (int j = 0; j < 8; j++){
            float v = acc[i][j] * sn[tx*8 + j];
            if (v > bv){ bv = v; bi = tx*8 + j; }
        }
        redv[(ly + i*16)*17 + tx] = bv;
        redi[(ly + i*16)*17 + tx] = bi;
    }
    __syncthreads();
    if (t < 32){
        float bv = -1e30f; int bi = 0;
        #pragma unroll
        for (int j = 0; j < 16; j++){
            float v = redv[t*17 + j];
            if (v > bv){ bv = v; bi = redi[t*17 + j]; }
        }
        g_idx[b*LL + l0 + t] = bi;
    }
}

// ============================================================================
// k_mp3: one mp_match epilogue (mode per launch).  grid 256.
// ============================================================================
__global__ void __launch_bounds__(256) k_mp3(
    const float* __restrict__ Lr, const float* __restrict__ hfw,
    const float* __restrict__ hbw, const float* __restrict__ Kmat,
    const float* __restrict__ Rr, float* __restrict__ out,
    int mode, int col0)
{
    __shared__ __align__(16) float P[16][68];
    __shared__ __align__(16) float Kc[64][68];
    __shared__ float hv[512];
    __shared__ float red[16][65];
    __shared__ int   sidx[16];

    int blk = blockIdx.x;
    int b = blk >> 3, l0 = (blk & 7) * 16;
    int t = threadIdx.x;

    if (mode == 0) { hv[t] = hfw[b*256 + t]; hv[256 + t] = hbw[b*256 + t]; }
    if (mode == 2 && t < 16) sidx[t] = g_idx[b*LL + l0 + t];

    int li = t >> 4, mj = t & 15;
    int srow = t >> 6, sk = t & 63;
    float cacc[4] = {0.f, 0.f, 0.f, 0.f};
    float acc[4]  = {0.f, 0.f, 0.f, 0.f};
    __syncthreads();

    for (int c = 0; c < 8; c++) {
        #pragma unroll
        for (int i = 0; i < 16; i++) {
            int f = i * 256 + t; int m = f >> 6, k = f & 63;
            Kc[m][k] = Kmat[(size_t)m * D + c*64 + k];
        }
        #pragma unroll
        for (int i = 0; i < 4; i++) {
            int row = i*4 + srow;
            int gl = b*LL + l0 + row;
            float lv = Lr[(size_t)gl * D + c*64 + sk];
            float av;
            if (mode == 0)      av = hv[c*64 + sk];
            else if (mode == 1) av = g_att[(size_t)gl * D + c*64 + sk];
            else                av = Rr[(size_t)(b*LR + sidx[row]) * D + c*64 + sk];
            float p = lv * av;
            P[row][sk] = p;
            cacc[i] += p;
        }
        __syncthreads();
        #pragma unroll
        for (int k4 = 0; k4 < 16; k4++) {
            float4 p4 = *(const float4*)&P[li][k4*4];
            #pragma unroll
            for (int j = 0; j < 4; j++) {
                float4 kv = *(const float4*)&Kc[j*16 + mj][k4*4];
                acc[j] = fmaf(p4.x, kv.x, fmaf(p4.y, kv.y, fmaf(p4.z, kv.z, fmaf(p4.w, kv.w, acc[j]))));
            }
        }
        __syncthreads();
    }
    #pragma unroll
    for (int i = 0; i < 4; i++) red[i*4 + srow][sk] = cacc[i];
    __syncthreads();
    if (t < 16) {
        float s = 0.f;
        #pragma unroll
        for (int k = 0; k < 64; k++) s += red[t][k];
        out[(size_t)(b*LL + l0 + t) * OC + col0] = tanhf(s);
    }
    #pragma unroll
    for (int j = 0; j < 4; j++)
        out[(size_t)(b*LL + l0 + li) * OC + col0 + 1 + j*16 + mj] = tanhf(acc[j]);
}

// ============================================================================
extern "C" void kernel_launch(void* const* d_in, const int* in_sizes, int n_in,
                              void* d_out, int out_size)
{
    const float* reps_lt = (const float*)d_in[0];
    const float* reps_rt = (const float*)d_in[3];
    const float* h_rt_fw = (const float*)d_in[4];
    const float* h_rt_bw = (const float*)d_in[5];
    const float* k_full  = (const float*)d_in[6];
    const float* k_mpW   = (const float*)d_in[7];
    const float* attn_w1 = (const float*)d_in[8];
    const float* diag_w  = (const float*)d_in[9];
    const float* k_attW  = (const float*)d_in[10];
    const float* k_maxW  = (const float*)d_in[11];
    float* out = (float*)d_out;

    static cudaStream_t s2 = 0, s3 = 0;
    static cudaEvent_t  eF = 0, eJ2 = 0, eJ3 = 0;
    if (!s2) {
        cudaFuncSetAttribute(k_mpool_mma, cudaFuncAttributeMaxDynamicSharedMemorySize, 100352);
        cudaFuncSetAttribute(k_algt_mma,  cudaFuncAttributeMaxDynamicSharedMemorySize, 131072);
        cudaFuncSetAttribute(k_pr_mma,    cudaFuncAttributeMaxDynamicSharedMemorySize, 131072);
        cudaStreamCreateWithFlags(&s2, cudaStreamNonBlocking);
        cudaStreamCreateWithFlags(&s3, cudaStreamNonBlocking);
        cudaEventCreateWithFlags(&eF,  cudaEventDisableTiming);
        cudaEventCreateWithFlags(&eJ2, cudaEventDisableTiming);
        cudaEventCreateWithFlags(&eJ3, cudaEventDisableTiming);
    }

    // main: split L first (needed by mpool AND algt_mma), then fork
    k_split<<<dim3(8, B), 256>>>(reps_lt, 0);
    cudaEventRecord(eF, 0);
    cudaStreamWaitEvent(s2, eF, 0);
    cudaStreamWaitEvent(s3, eF, 0);

    // main stream: dominant tensor-core chain (cols 65..128)
    k_mpool_mma<<<dim3(64, B), 256, 100352>>>(reps_rt, k_mpW, out);

    // s2: attentive path -> mp3 mode1 (cols 129..193)
    k_splitRT<<<dim3(8, B), 256, 0, s2>>>(reps_rt);
    k_split<<<dim3(8, B), 256, 0, s2>>>(reps_rt, 1);
    k_splitW<<<dim3(8, 8), 256, 0, s2>>>(attn_w1);
    k_algt_mma<<<64, 256, 131072, s2>>>(diag_w);
    k_score<<<dim3(4, B), 256, 0, s2>>>();
    k_pr_mma<<<dim3(4, B), 256, 131072, s2>>>();
    k_mp3<<<256, 256, 0, s2>>>(reps_lt, h_rt_fw, h_rt_bw, k_attW, reps_rt, out, 1, 129);

    // s3: full match (cols 0..64) + max-attentive -> mp3 mode2 (cols 194..258)
    k_mp3<<<256, 256, 0, s3>>>(reps_lt, h_rt_fw, h_rt_bw, k_full, reps_rt, out, 0, 0);
    k_nrt<<<512, 256, 0, s3>>>(reps_rt);
    k_idx<<<dim3(4, B), 256, 0, s3>>>(reps_lt, reps_rt);
    k_mp3<<<256, 256, 0, s3>>>(reps_lt, h_rt_fw, h_rt_bw, k_maxW, reps_rt, out, 2, 194);

    // join side streams back into the main stream
    cudaEventRecord(eJ2, s2);
    cudaEventRecord(eJ3, s3);
    cudaStreamWaitEvent(0, eJ2, 0);
    cudaStreamWaitEvent(0, eJ3, 0);
}

// round 15
// speedup vs baseline: 1.8147x; 1.4020x over previous
#include <cuda_runtime.h>
#include <math.h>
#include <stdint.h>

#define B   32
#define LL  128
#define LR  128
#define D   512
#define A   128
#define OC  259   // 1+64 | 64 | 1+64 | 1+64

// ---- scratch (static device globals; no runtime allocation) ----
__device__ float g_algt[(B*LL + B*LR) * A];
__device__ float g_att[B*LL*D];
__device__ float g_invnrt[B*LR];
__device__ int   g_idx[B*LL];
// pre-split bf16 hi/lo swizzled tiles: (b,chunk) tiles of 128 rows x 128B
__device__ __align__(16) unsigned char g_Lh[B*8*16384];
__device__ __align__(16) unsigned char g_Ll[B*8*16384];
__device__ __align__(16) unsigned char g_Lf[B*8*16384];   // fp16 single (mpool A)
__device__ __align__(16) unsigned char g_Rh[B*8*16384];
__device__ __align__(16) unsigned char g_Rl[B*8*16384];
// W1 transposed to B-operand tiles: 8 chunks x (128 a-rows x 64 d) hi/lo
__device__ __align__(16) unsigned char g_Wh[8*16384];
__device__ __align__(16) unsigned char g_Wl[8*16384];
// softmax probs as A-operand tiles: (b, r-chunk) of 128 l-rows x 64 r
__device__ __align__(16) unsigned char g_Ph[B*2*16384];
__device__ __align__(16) unsigned char g_Pl[B*2*16384];
// R transposed to B-operand tiles: (b, nt*2+rc): 128 d-rows x 64 r
__device__ __align__(16) unsigned char g_RTh[B*8*16384];
__device__ __align__(16) unsigned char g_RTl[B*8*16384];

__device__ __forceinline__ uint32_t swz(uint32_t x){ return x ^ ((x >> 3) & 0x70u); }
__device__ __forceinline__ uint32_t smem_u32(const void* p){
    uint32_t a;
    asm("{ .reg .u64 t; cvta.to.shared.u64 t, %1; cvt.u32.u64 %0, t; }" : "=r"(a) : "l"(p));
    return a;
}
__device__ __forceinline__ void split2(float x0, float x1, uint32_t& h, uint32_t& l){
    asm("cvt.rn.bf16x2.f32 %0, %1, %2;" : "=r"(h) : "f"(x1), "f"(x0));
    float h0 = __uint_as_float(h << 16), h1 = __uint_as_float(h & 0xffff0000u);
    asm("cvt.rn.bf16x2.f32 %0, %1, %2;" : "=r"(l) : "f"(x1 - h1), "f"(x0 - h0));
}
__device__ __forceinline__ uint32_t pack_f16(float x0, float x1){
    uint32_t h;
    asm("cvt.rn.f16x2.f32 %0, %1, %2;" : "=r"(h) : "f"(x1), "f"(x0));
    return h;
}

#define LDSM4(r0,r1,r2,r3,addr) \
    asm volatile("ldmatrix.sync.aligned.m8n8.x4.shared.b16 {%0,%1,%2,%3}, [%4];" \
        : "=r"(r0),"=r"(r1),"=r"(r2),"=r"(r3) : "r"(addr))
#define CP16(s,g) \
    asm volatile("cp.async.cg.shared.global [%0], [%1], 16;" :: "r"(s), "l"(g))
#define CPCOMMIT() asm volatile("cp.async.commit_group;")
#define CPWAIT1()  asm volatile("cp.async.wait_group 1;")
#define CPWAIT0()  asm volatile("cp.async.wait_group 0;")

__device__ __forceinline__ void mma_bf16(float* d, const uint32_t* a, const uint32_t* b){
    asm volatile("mma.sync.aligned.m16n8k16.row.col.f32.bf16.bf16.f32 "
        "{%0,%1,%2,%3}, {%4,%5,%6,%7}, {%8,%9}, {%0,%1,%2,%3};"
        : "+f"(d[0]),"+f"(d[1]),"+f"(d[2]),"+f"(d[3])
        : "r"(a[0]),"r"(a[1]),"r"(a[2]),"r"(a[3]), "r"(b[0]),"r"(b[1]));
}
__device__ __forceinline__ void mma_f16(float* d, const uint32_t* a, const uint32_t* b){
    asm volatile("mma.sync.aligned.m16n8k16.row.col.f32.f16.f16.f32 "
        "{%0,%1,%2,%3}, {%4,%5,%6,%7}, {%8,%9}, {%0,%1,%2,%3};"
        : "+f"(d[0]),"+f"(d[1]),"+f"(d[2]),"+f"(d[3])
        : "r"(a[0]),"r"(a[1]),"r"(a[2]),"r"(a[3]), "r"(b[0]),"r"(b[1]));
}

// ============================================================================
// k_split: X (fp32) -> bf16 hi/lo tiles (+ fp16 tile for L). grid (8, B).
// ============================================================================
__global__ void __launch_bounds__(256) k_split(const float* __restrict__ X, int which)
{
    int c = blockIdx.x, b = blockIdx.y, t = threadIdx.x;
    const float* Xb = X + ((size_t)b << 16) + c*64;
    size_t tile = ((size_t)(b*8 + c)) << 14;
    unsigned char* dh = (which ? g_Rh : g_Lh) + tile;
    unsigned char* dl = (which ? g_Rl : g_Ll) + tile;
    unsigned char* df = g_Lf + tile;
    #pragma unroll
    for (int i = 0; i < 4; i++){
        int f = i*256 + t; int row = f >> 3, q = f & 7;
        const float* src = Xb + (size_t)row*512 + q*8;
        float4 v0 = *(const float4*)src, v1 = *(const float4*)(src + 4);
        uint32_t h01,l01,h23,l23,h45,l45,h67,l67;
        split2(v0.x, v0.y, h01, l01);
        split2(v0.z, v0.w, h23, l23);
        split2(v1.x, v1.y, h45, l45);
        split2(v1.z, v1.w, h67, l67);
        uint32_t off = swz((uint32_t)(row*128 + q*16));
        *(uint4*)(dh + off) = make_uint4(h01, h23, h45, h67);
        *(uint4*)(dl + off) = make_uint4(l01, l23, l45, l67);
        if (!which){
            uint4 fp;
            fp.x = pack_f16(v0.x, v0.y); fp.y = pack_f16(v0.z, v0.w);
            fp.z = pack_f16(v1.x, v1.y); fp.w = pack_f16(v1.z, v1.w);
            *(uint4*)(df + off) = fp;
        }
    }
}

// ============================================================================
// k_splitW: W1 [d=512][a=128] -> transposed B tiles. grid (8, 8).
// ============================================================================
__global__ void __launch_bounds__(256) k_splitW(const float* __restrict__ W1)
{
    int c = blockIdx.x, t = threadIdx.x;
    size_t tile = ((size_t)c) << 14;
    int i = blockIdx.y;
    {
        int f = i*256 + t; int row = f >> 4, q = f & 15;
        int d0 = c*64 + q*4;
        float w0 = W1[(size_t)(d0+0)*A + row];
        float w1 = W1[(size_t)(d0+1)*A + row];
        float w2 = W1[(size_t)(d0+2)*A + row];
        float w3 = W1[(size_t)(d0+3)*A + row];
        uint32_t h01,l01,h23,l23;
        split2(w0, w1, h01, l01);
        split2(w2, w3, h23, l23);
        uint32_t off = swz((uint32_t)(row*128 + q*8));
        *(uint2*)(g_Wh + tile + off) = make_uint2(h01, h23);
        *(uint2*)(g_Wl + tile + off) = make_uint2(l01, l23);
    }
}

// ============================================================================
// k_splitRT: R -> transposed B tiles (rows=d, k=r). grid (8, B); j = nt*2+rc.
// ============================================================================
__global__ void __launch_bounds__(256) k_splitRT(const float* __restrict__ Rr)
{
    __shared__ __align__(16) float Rsm[64*132];
    int j = blockIdx.x, b = blockIdx.y, t = threadIdx.x;
    int nt = j >> 1, rc = j & 1;
    const float* src = Rr + ((size_t)b << 16) + (size_t)(rc*64)*512 + nt*128;
    #pragma unroll
    for (int i = 0; i < 8; i++){
        int f = i*256 + t; int row = f >> 5, dc = (f & 31)*4;
        *(float4*)&Rsm[row*132 + dc] = *(const float4*)(src + (size_t)row*512 + dc);
    }
    __syncthreads();
    size_t tile = ((size_t)(b*8 + j)) << 14;
    #pragma unroll
    for (int i = 0; i < 4; i++){
        int f = i*256 + t; int drow = f >> 3, oct = f & 7;
        int r0 = oct*8;
        float v[8];
        #pragma unroll
        for (int k = 0; k < 8; k++) v[k] = Rsm[(r0+k)*132 + drow];
        uint32_t h01,l01,h23,l23,h45,l45,h67,l67;
        split2(v[0],v[1],h01,l01); split2(v[2],v[3],h23,l23);
        split2(v[4],v[5],h45,l45); split2(v[6],v[7],h67,l67);
        uint32_t off = swz((uint32_t)(drow*128 + oct*16));
        *(uint4*)(g_RTh + tile + off) = make_uint4(h01,h23,h45,h67);
        *(uint4*)(g_RTl + tile + off) = make_uint4(l01,l23,l45,l67);
    }
}

// ============================================================================
// k_mpool_mma: CTA = (m, b).  C[l,r] = sum_d L[l,d]*(R[r,d]*K_m[d]).
// SINGLE-term fp16 (legacy mma.sync is rate-bound; 3x fewer MMAs).
// A = L fp16 tiles (cp.async dbl-buffered), B = fp16(R*K_m) built in smem.
// out[b,l,65+m] = tanh(max_r C).
// dyn smem: A[2] 32K | Bf 16K | sK 2K = 51200 B, occ 2 (regs).
// ============================================================================
__global__ void __launch_bounds__(256, 2) k_mpool_mma(
    const float* __restrict__ Rr, const float* __restrict__ Kmp,
    float* __restrict__ out)
{
    extern __shared__ __align__(16) unsigned char dyn[];
    int m = blockIdx.x, b = blockIdx.y;
    int t = threadIdx.x, wid = t >> 5, lane = t & 31;
    uint32_t base = smem_u32(dyn);
    uint32_t Abuf[2] = {base, base + 16384};
    uint32_t Bf = base + 32768;
    float* sK = (float*)(dyn + 49152);
    for (int i = t; i < 512; i += 256) sK[i] = Kmp[(size_t)m*512 + i];

    {
        const unsigned char* gf = g_Lf + (((size_t)(b*8)) << 14);
        #pragma unroll
        for (int i = 0; i < 4; i++){
            uint32_t o = (uint32_t)(i*256 + t) * 16;
            CP16(Abuf[0] + o, gf + o);
        }
        CPCOMMIT();
    }
    __syncthreads();

    int wl = wid >> 2, wn = wid & 3;
    float acc[4][4][4];
    #pragma unroll
    for (int i = 0; i < 4; i++)
        #pragma unroll
        for (int j = 0; j < 4; j++)
            #pragma unroll
            for (int k = 0; k < 4; k++) acc[i][j][k] = 0.f;

    int rowA = lane & 15;
    int cbA  = lane >> 4;
    int rowB = ((lane >> 4) & 1) * 8 + (lane & 7);
    int cbB  = (lane >> 3) & 1;

    const float* Rb = Rr + ((size_t)b << 16);
    int rrow = t >> 3, rq = t & 7;

    for (int c = 0; c < 8; c++){
        if (c < 7){
            uint32_t nb = Abuf[(c+1) & 1];
            const unsigned char* gf = g_Lf + (((size_t)(b*8 + c+1)) << 14);
            #pragma unroll
            for (int i = 0; i < 4; i++){
                uint32_t o = (uint32_t)(i*256 + t) * 16;
                CP16(nb + o, gf + o);
            }
            CPCOMMIT();
        }
        // build B = fp16(R*K_m); 8 elements per thread per iter
        {
            float4 k0 = *(const float4*)(sK + c*64 + rq*8);
            float4 k1 = *(const float4*)(sK + c*64 + rq*8 + 4);
            #pragma unroll
            for (int i = 0; i < 4; i++){
                int row = rrow + i*32;
                const float* src = Rb + (size_t)row*512 + c*64 + rq*8;
                float4 r0 = *(const float4*)src, r1 = *(const float4*)(src + 4);
                uint32_t p0 = pack_f16(r0.x*k0.x, r0.y*k0.y);
                uint32_t p1 = pack_f16(r0.z*k0.z, r0.w*k0.w);
                uint32_t p2 = pack_f16(r1.x*k1.x, r1.y*k1.y);
                uint32_t p3 = pack_f16(r1.z*k1.z, r1.w*k1.w);
                uint32_t off = swz((uint32_t)(row*128 + rq*16));
                asm volatile("st.shared.v4.b32 [%0], {%1,%2,%3,%4};"
                             :: "r"(Bf+off), "r"(p0), "r"(p1), "r"(p2), "r"(p3));
            }
        }
        if (c < 7) { CPWAIT1(); } else { CPWAIT0(); }
        __syncthreads();

        uint32_t Af = Abuf[c & 1];
        #pragma unroll
        for (int ks = 0; ks < 4; ks++){
            uint32_t aoffs[4], boffs[2];
            #pragma unroll
            for (int mt = 0; mt < 4; mt++)
                aoffs[mt] = swz((uint32_t)((wl*64 + mt*16 + rowA)*128 + ks*32 + cbA*16));
            #pragma unroll
            for (int jp = 0; jp < 2; jp++)
                boffs[jp] = swz((uint32_t)((wn*32 + jp*16 + rowB)*128 + ks*32 + cbB*16));

            uint32_t bf_[4][2];
            #pragma unroll
            for (int jp = 0; jp < 2; jp++)
                LDSM4(bf_[jp*2][0], bf_[jp*2][1], bf_[jp*2+1][0], bf_[jp*2+1][1], Bf + boffs[jp]);
            uint32_t af_[4][4];
            #pragma unroll
            for (int mt = 0; mt < 4; mt++)
                LDSM4(af_[mt][0], af_[mt][1], af_[mt][2], af_[mt][3], Af + aoffs[mt]);
            #pragma unroll
            for (int mt = 0; mt < 4; mt++)
                #pragma unroll
                for (int nt = 0; nt < 4; nt++)
                    mma_f16(acc[mt][nt], af_[mt], bf_[nt]);
        }
        __syncthreads();
    }

    float* red = (float*)dyn;
    int g = lane >> 2, tg = lane & 3;
    #pragma unroll
    for (int mt = 0; mt < 4; mt++){
        float m0 = -1e30f, m1 = -1e30f;
        #pragma unroll
        for (int nt = 0; nt < 4; nt++){
            m0 = fmaxf(m0, fmaxf(acc[mt][nt][0], acc[mt][nt][1]));
            m1 = fmaxf(m1, fmaxf(acc[mt][nt][2], acc[mt][nt][3]));
        }
        m0 = fmaxf(m0, __shfl_xor_sync(0xffffffffu, m0, 1));
        m0 = fmaxf(m0, __shfl_xor_sync(0xffffffffu, m0, 2));
        m1 = fmaxf(m1, __shfl_xor_sync(0xffffffffu, m1, 1));
        m1 = fmaxf(m1, __shfl_xor_sync(0xffffffffu, m1, 2));
        if (tg == 0){
            red[(wl*64 + mt*16 + g)*4 + wn]     = m0;
            red[(wl*64 + mt*16 + g + 8)*4 + wn] = m1;
        }
    }
    __syncthreads();
    if (t < 128){
        float v = fmaxf(fmaxf(red[t*4], red[t*4+1]), fmaxf(red[t*4+2], red[t*4+3]));
        out[((size_t)(b*LL + t))*OC + 65 + m] = tanhf(v);
    }
}

// ============================================================================
// k_algt_mma: tanh([L;R] @ W1) (*diag for L rows).  grid 64, dbl-buf 131072 B.
// (3-term bf16 — precision-critical inputs to softmax/attention)
// ============================================================================
__global__ void __launch_bounds__(256) k_algt_mma(const float* __restrict__ diag)
{
    extern __shared__ __align__(16) unsigned char dyn[];
    __shared__ float sdiag[128];
    int bi = blockIdx.x;
    int isL = (bi < 32) ? 1 : 0;
    int b = isL ? bi : bi - 32;
    int t = threadIdx.x, wid = t >> 5, lane = t & 31;
    uint32_t base = smem_u32(dyn);
    uint32_t buf[2] = {base, base + 65536};

    if (t < 128) sdiag[t] = diag[t];

    const unsigned char* srcH = isL ? g_Lh : g_Rh;
    const unsigned char* srcL = isL ? g_Ll : g_Rl;

    {
        const unsigned char* ah = srcH + (((size_t)(b*8)) << 14);
        const unsigned char* al = srcL + (((size_t)(b*8)) << 14);
        #pragma unroll
        for (int i = 0; i < 4; i++){
            uint32_t o = (uint32_t)(i*256 + t) * 16;
            CP16(buf[0] + o,         ah + o);
            CP16(buf[0] + 16384 + o, al + o);
            CP16(buf[0] + 32768 + o, g_Wh + o);
            CP16(buf[0] + 49152 + o, g_Wl + o);
        }
        CPCOMMIT();
    }

    int wl = wid >> 2, wn = wid & 3;
    float acc[4][4][4];
    #pragma unroll
    for (int i = 0; i < 4; i++)
        #pragma unroll
        for (int j = 0; j < 4; j++)
            #pragma unroll
            for (int k = 0; k < 4; k++) acc[i][j][k] = 0.f;

    int rowA = lane & 15;
    int cbA  = lane >> 4;
    int rowB = ((lane >> 4) & 1) * 8 + (lane & 7);
    int cbB  = (lane >> 3) & 1;

    for (int c = 0; c < 8; c++){
        if (c < 7){
            uint32_t nb = buf[(c+1) & 1];
            const unsigned char* ah = srcH + (((size_t)(b*8 + c+1)) << 14);
            const unsigned char* al = srcL + (((size_t)(b*8 + c+1)) << 14);
            const unsigned char* wh = g_Wh + (((size_t)(c+1)) << 14);
            const unsigned char* wlp = g_Wl + (((size_t)(c+1)) << 14);
            #pragma unroll
            for (int i = 0; i < 4; i++){
                uint32_t o = (uint32_t)(i*256 + t) * 16;
                CP16(nb + o,         ah + o);
                CP16(nb + 16384 + o, al + o);
                CP16(nb + 32768 + o, wh + o);
                CP16(nb + 49152 + o, wlp + o);
            }
            CPCOMMIT();
        }
        if (c < 7) { CPWAIT1(); } else { CPWAIT0(); }
        __syncthreads();

        uint32_t Ah = buf[c & 1], Al = Ah + 16384, Wh = Ah + 32768, Wlb = Ah + 49152;
        #pragma unroll
        for (int ks = 0; ks < 4; ks++){
            uint32_t aoffs[4], boffs[2];
            #pragma unroll
            for (int mt = 0; mt < 4; mt++)
                aoffs[mt] = swz((uint32_t)((wl*64 + mt*16 + rowA)*128 + ks*32 + cbA*16));
            #pragma unroll
            for (int jp = 0; jp < 2; jp++)
                boffs[jp] = swz((uint32_t)((wn*32 + jp*16 + rowB)*128 + ks*32 + cbB*16));

            uint32_t bh_[4][2];
            #pragma unroll
            for (int jp = 0; jp < 2; jp++)
                LDSM4(bh_[jp*2][0], bh_[jp*2][1], bh_[jp*2+1][0], bh_[jp*2+1][1], Wh + boffs[jp]);
            {
                uint32_t al_[4][4];
                #pragma unroll
                for (int mt = 0; mt < 4; mt++)
                    LDSM4(al_[mt][0], al_[mt][1], al_[mt][2], al_[mt][3], Al + aoffs[mt]);
                #pragma unroll
                for (int mt = 0; mt < 4; mt++)
                    #pragma unroll
                    for (int nt = 0; nt < 4; nt++)
                        mma_bf16(acc[mt][nt], al_[mt], bh_[nt]);
            }
            uint32_t ah_[4][4];
            #pragma unroll
            for (int mt = 0; mt < 4; mt++)
                LDSM4(ah_[mt][0], ah_[mt][1], ah_[mt][2], ah_[mt][3], Ah + aoffs[mt]);
            #pragma unroll
            for (int mt = 0; mt < 4; mt++)
                #pragma unroll
                for (int nt = 0; nt < 4; nt++)
                    mma_bf16(acc[mt][nt], ah_[mt], bh_[nt]);
            {
                uint32_t bl_[4][2];
                #pragma unroll
                for (int jp = 0; jp < 2; jp++)
                    LDSM4(bl_[jp*2][0], bl_[jp*2][1], bl_[jp*2+1][0], bl_[jp*2+1][1], Wlb + boffs[jp]);
                #pragma unroll
                for (int mt = 0; mt < 4; mt++)
                    #pragma unroll
                    for (int nt = 0; nt < 4; nt++)
                        mma_bf16(acc[mt][nt], ah_[mt], bl_[nt]);
            }
        }
        __syncthreads();
    }

    int g = lane >> 2, tg = lane & 3;
    size_t rbase = (size_t)bi * 128;
    #pragma unroll
    for (int mt = 0; mt < 4; mt++){
        int r0 = wl*64 + mt*16 + g, r1 = r0 + 8;
        #pragma unroll
        for (int nt = 0; nt < 4; nt++){
            int col = wn*32 + nt*8 + tg*2;
            float d0 = isL ? sdiag[col] : 1.f;
            float d1 = isL ? sdiag[col+1] : 1.f;
            float2 v0 = make_float2(tanhf(acc[mt][nt][0])*d0, tanhf(acc[mt][nt][1])*d1);
            float2 v1 = make_float2(tanhf(acc[mt][nt][2])*d0, tanhf(acc[mt][nt][3])*d1);
            *(float2*)&g_algt[(rbase + r0)*A + col] = v0;
            *(float2*)&g_algt[(rbase + r1)*A + col] = v1;
        }
    }
}

// ============================================================================
// k_score: register-tiled scores + softmax -> bf16 hi/lo P-tiles.
// grid (4, B): 32 l x 128 r.
// ============================================================================
__global__ void __launch_bounds__(256) k_score()
{
    __shared__ float Ls[16*36];
    __shared__ float Rs[16*132];
    __shared__ __align__(16) float S[32*132];

    int b = blockIdx.y, l0 = blockIdx.x*32, t = threadIdx.x;
    int ly = t >> 4, tx = t & 15;
    float acc[2][8];
    #pragma unroll
    for (int i = 0; i < 2; i++)
        #pragma unroll
        for (int j = 0; j < 8; j++) acc[i][j] = 0.f;

    const float* Lb = g_algt + (size_t)(b*LL + l0) * A;
    const float* Rb = g_algt + (size_t)(B*LL + b*LR) * A;

    for (int kc = 0; kc < 8; kc++){
        __syncthreads();
        {
            int row = t >> 3, c2 = (t & 7)*2;
            float2 v = *(const float2*)(Lb + (size_t)row*A + kc*16 + c2);
            Ls[c2*36 + row] = v.x;
            Ls[(c2+1)*36 + row] = v.y;
        }
        {
            int row = t >> 1, c8 = (t & 1)*8;
            const float* src = Rb + (size_t)row*A + kc*16 + c8;
            float4 v0 = *(const float4*)src, v1 = *(const float4*)(src + 4);
            Rs[(c8+0)*132 + row] = v0.x; Rs[(c8+1)*132 + row] = v0.y;
            Rs[(c8+2)*132 + row] = v0.z; Rs[(c8+3)*132 + row] = v0.w;
            Rs[(c8+4)*132 + row] = v1.x; Rs[(c8+5)*132 + row] = v1.y;
            Rs[(c8+6)*132 + row] = v1.z; Rs[(c8+7)*132 + row] = v1.w;
        }
        __syncthreads();
        #pragma unroll
        for (int k = 0; k < 16; k++){
            float a0 = Ls[k*36 + ly], a1 = Ls[k*36 + ly + 16];
            float4 b0 = *(const float4*)&Rs[k*132 + tx*8];
            float4 b1 = *(const float4*)&Rs[k*132 + tx*8 + 4];
            float bv[8] = {b0.x,b0.y,b0.z,b0.w,b1.x,b1.y,b1.z,b1.w};
            #pragma unroll
            for (int j = 0; j < 8; j++){
                acc[0][j] = fmaf(a0, bv[j], acc[0][j]);
                acc[1][j] = fmaf(a1, bv[j], acc[1][j]);
            }
        }
    }
    #pragma unroll
    for (int i = 0; i < 2; i++)
        #pragma unroll
        for (int j = 0; j < 8; j++)
            S[(ly + i*16)*132 + tx*8 + j] = acc[i][j];
    __syncthreads();

    int w = t >> 5, lane = t & 31;
    #pragma unroll
    for (int rr = w*4; rr < w*4 + 4; rr++){
        float v0 = S[rr*132+lane], v1 = S[rr*132+lane+32],
              v2 = S[rr*132+lane+64], v3 = S[rr*132+lane+96];
        float m0 = fmaxf(fmaxf(v0,v1), fmaxf(v2,v3));
        #pragma unroll
        for (int off = 16; off; off >>= 1) m0 = fmaxf(m0, __shfl_xor_sync(0xffffffffu, m0, off));
        float e0 = expf(v0-m0), e1 = expf(v1-m0), e2 = expf(v2-m0), e3 = expf(v3-m0);
        float sum = e0+e1+e2+e3;
        #pragma unroll
        for (int off = 16; off; off >>= 1) sum += __shfl_xor_sync(0xffffffffu, sum, off);
        float inv = 1.f / sum;
        S[rr*132+lane] = e0*inv; S[rr*132+lane+32] = e1*inv;
        S[rr*132+lane+64] = e2*inv; S[rr*132+lane+96] = e3*inv;
    }
    __syncthreads();

    #pragma unroll
    for (int it = 0; it < 2; it++){
        int f = it*256 + t;
        int row = f >> 4, oct = f & 15;
        int c = oct >> 3;
        const float* sp = &S[row*132 + oct*8];
        float4 p0 = *(const float4*)sp, p1 = *(const float4*)(sp + 4);
        uint32_t h01,l01,h23,l23,h45,l45,h67,l67;
        split2(p0.x,p0.y,h01,l01); split2(p0.z,p0.w,h23,l23);
        split2(p1.x,p1.y,h45,l45); split2(p1.z,p1.w,h67,l67);
        int l = l0 + row;
        uint32_t off = swz((uint32_t)(l*128 + (oct & 7)*16));
        size_t tile = ((size_t)(b*2 + c)) << 14;
        *(uint4*)(g_Ph + tile + off) = make_uint4(h01,h23,h45,h67);
        *(uint4*)(g_Pl + tile + off) = make_uint4(l01,l23,l45,l67);
    }
}

// ============================================================================
// k_pr_mma: att = P @ R via 3-term split bf16 MMA.  grid (4 d-tiles, B).
// ============================================================================
__global__ void __launch_bounds__(256) k_pr_mma()
{
    extern __shared__ __align__(16) unsigned char dyn[];
    int nt = blockIdx.x, b = blockIdx.y;
    int t = threadIdx.x, wid = t >> 5, lane = t & 31;
    uint32_t base = smem_u32(dyn);

    {
        const unsigned char* ph = g_Ph + (((size_t)(b*2)) << 14);
        const unsigned char* pl = g_Pl + (((size_t)(b*2)) << 14);
        const unsigned char* bh = g_RTh + (((size_t)(b*8 + nt*2)) << 14);
        const unsigned char* bl = g_RTl + (((size_t)(b*8 + nt*2)) << 14);
        #pragma unroll
        for (int i = 0; i < 8; i++){
            uint32_t o = (uint32_t)(i*256 + t) * 16;
            CP16(base + o,          ph + o);
            CP16(base + 32768 + o,  pl + o);
            CP16(base + 65536 + o,  bh + o);
            CP16(base + 98304 + o,  bl + o);
        }
        CPCOMMIT(); CPWAIT0();
    }
    __syncthreads();

    int wl = wid >> 2, wn = wid & 3;
    float acc[4][4][4];
    #pragma unroll
    for (int i = 0; i < 4; i++)
        #pragma unroll
        for (int j = 0; j < 4; j++)
            #pragma unroll
            for (int k = 0; k < 4; k++) acc[i][j][k] = 0.f;

    int rowA = lane & 15;
    int cbA  = lane >> 4;
    int rowB = ((lane >> 4) & 1) * 8 + (lane & 7);
    int cbB  = (lane >> 3) & 1;

    for (int ks8 = 0; ks8 < 8; ks8++){
        int ch = ks8 >> 2, ks = ks8 & 3;
        uint32_t Ah = base + ch*16384,         Al  = base + 32768 + ch*16384;
        uint32_t Bh = base + 65536 + ch*16384, Blb = base + 98304 + ch*16384;
        uint32_t aoffs[4], boffs[2];
        #pragma unroll
        for (int mt = 0; mt < 4; mt++)
            aoffs[mt] = swz((uint32_t)((wl*64 + mt*16 + rowA)*128 + ks*32 + cbA*16));
        #pragma unroll
        for (int jp = 0; jp < 2; jp++)
            boffs[jp] = swz((uint32_t)((wn*32 + jp*16 + rowB)*128 + ks*32 + cbB*16));

        uint32_t bh_[4][2];
        #pragma unroll
        for (int jp = 0; jp < 2; jp++)
            LDSM4(bh_[jp*2][0], bh_[jp*2][1], bh_[jp*2+1][0], bh_[jp*2+1][1], Bh + boffs[jp]);
        {
            uint32_t al_[4][4];
            #pragma unroll
            for (int mt = 0; mt < 4; mt++)
                LDSM4(al_[mt][0], al_[mt][1], al_[mt][2], al_[mt][3], Al + aoffs[mt]);
            #pragma unroll
            for (int mt = 0; mt < 4; mt++)
                #pragma unroll
                for (int n2 = 0; n2 < 4; n2++)
                    mma_bf16(acc[mt][n2], al_[mt], bh_[n2]);
        }
        uint32_t ah_[4][4];
        #pragma unroll
        for (int mt = 0; mt < 4; mt++)
            LDSM4(ah_[mt][0], ah_[mt][1], ah_[mt][2], ah_[mt][3], Ah + aoffs[mt]);
        #pragma unroll
        for (int mt = 0; mt < 4; mt++)
            #pragma unroll
            for (int n2 = 0; n2 < 4; n2++)
                mma_bf16(acc[mt][n2], ah_[mt], bh_[n2]);
        {
            uint32_t bl_[4][2];
            #pragma unroll
            for (int jp = 0; jp < 2; jp++)
                LDSM4(bl_[jp*2][0], bl_[jp*2][1], bl_[jp*2+1][0], bl_[jp*2+1][1], Blb + boffs[jp]);
            #pragma unroll
            for (int mt = 0; mt < 4; mt++)
                #pragma unroll
                for (int n2 = 0; n2 < 4; n2++)
                    mma_bf16(acc[mt][n2], ah_[mt], bl_[n2]);
        }
    }

    int g = lane >> 2, tg = lane & 3;
    float* ob = g_att + ((size_t)(b*LL))*D + nt*128;
    #pragma unroll
    for (int mt = 0; mt < 4; mt++){
        int r0 = wl*64 + mt*16 + g, r1 = r0 + 8;
        #pragma unroll
        for (int n2 = 0; n2 < 4; n2++){
            int col = wn*32 + n2*8 + tg*2;
            *(float2*)&ob[(size_t)r0*D + col] = make_float2(acc[mt][n2][0], acc[mt][n2][1]);
            *(float2*)&ob[(size_t)r1*D + col] = make_float2(acc[mt][n2][2], acc[mt][n2][3]);
        }
    }
}

// ============================================================================
// k_nrt: inv right norms, grid 512 (one warp per row)
// ============================================================================
__global__ void k_nrt(const float* __restrict__ Rr)
{
    int blk = blockIdx.x;
    int b = blk >> 4, r = (blk & 15)*8 + (threadIdx.x >> 5);
    int lane = threadIdx.x & 31;
    const float* row = Rr + (size_t)(b*LR + r) * D;
    float s = 0.f;
    #pragma unroll 4
    for (int i = lane; i < D; i += 32){ float v = row[i]; s = fmaf(v, v, s); }
    #pragma unroll
    for (int off = 16; off; off >>= 1) s += __shfl_xor_sync(0xffffffffu, s, off);
    if (!lane) g_invnrt[b*LR + r] = rsqrtf(fmaxf(s, 1e-6f));
}

// ============================================================================
// k_idx: argmax_r cosine(L[l], R[r]).  block = 32 l x 128 r, grid (4, B).
// ============================================================================
__global__ void __launch_bounds__(256) k_idx(
    const float* __restrict__ Lr, const float* __restrict__ Rr)
{
    __shared__ float Ls[16*36];
    __shared__ float Rs[16*132];
    __shared__ float sn[128];
    __shared__ float redv[32*17];
    __shared__ int   redi[32*17];

    int b = blockIdx.y, l0 = blockIdx.x*32, t = threadIdx.x;
    if (t < 128) sn[t] = g_invnrt[b*LR + t];

    int ly = t >> 4, tx = t & 15;
    float acc[2][8];
    #pragma unroll
    for (int i = 0; i < 2; i++)
        #pragma unroll
        for (int j = 0; j < 8; j++) acc[i][j] = 0.f;

    const float* Lb = Lr + (size_t)(b*LL + l0) * D;
    const float* Rb = Rr + ((size_t)b << 16);

    for (int kc = 0; kc < 32; kc++){
        __syncthreads();
        {
            int row = t >> 3, c2 = (t & 7)*2;
            float2 v = *(const float2*)(Lb + (size_t)row*D + kc*16 + c2);
            Ls[c2*36 + row] = v.x;
            Ls[(c2+1)*36 + row] = v.y;
        }
        {
            int row = t >> 1, c8 = (t & 1)*8;
            const float* src = Rb + (size_t)row*D + kc*16 + c8;
            float4 v0 = *(const float4*)src, v1 = *(const float4*)(src + 4);
            Rs[(c8+0)*132 + row] = v0.x; Rs[(c8+1)*132 + row] = v0.y;
            Rs[(c8+2)*132 + row] = v0.z; Rs[(c8+3)*132 + row] = v0.w;
            Rs[(c8+4)*132 + row] = v1.x; Rs[(c8+5)*132 + row] = v1.y;
            Rs[(c8+6)*132 + row] = v1.z; Rs[(c8+7)*132 + row] = v1.w;
        }
        __syncthreads();
        #pragma unroll
        for (int k = 0; k < 16; k++){
            float a0 = Ls[k*36 + ly], a1 = Ls[k*36 + ly + 16];
            float4 b0 = *(const float4*)&Rs[k*132 + tx*8];
            float4 b1 = *(const float4*)&Rs[k*132 + tx*8 + 4];
            float bv[8] = {b0.x,b0.y,b0.z,b0.w,b1.x,b1.y,b1.z,b1.w};
            #pragma unroll
            for (int j = 0; j < 8; j++){
                acc[0][j] = fmaf(a0, bv[j], acc[0][j]);
                acc[1][j] = fmaf(a1, bv[j], acc[1][j]);
            }
        }
    }
    #pragma unroll
    for (int i = 0; i < 2; i++){
        float bv = -1e30f; int bi = 0;
        #pragma unroll
        for (int j = 0; j < 8; j++){
            float v = acc[i][j] * sn[tx*8 + j];
            if (v > bv){ bv = v; bi = tx*8 + j; }
        }
        redv[(ly + i*16)*17 + tx] = bv;
        redi[(ly + i*16)*17 + tx] = bi;
    }
    __syncthreads();
    if (t < 32){
        float bv = -1e30f; int bi = 0;
        #pragma unroll
        for (int j = 0; j < 16; j++){
            float v = redv[t*17 + j];
            if (v > bv){ bv = v; bi = redi[t*17 + j]; }
        }
        g_idx[b*LL + l0 + t] = bi;
    }
}

// ============================================================================
// k_mp3: one mp_match epilogue (mode per launch).  grid 256.
// ============================================================================
__global__ void __launch_bounds__(256) k_mp3(
    const float* __restrict__ Lr, const float* __restrict__ hfw,
    const float* __restrict__ hbw, const float* __restrict__ Kmat,
    const float* __restrict__ Rr, float* __restrict__ out,
    int mode, int col0)
{
    __shared__ __align__(16) float P[16][68];
    __shared__ __align__(16) float Kc[64][68];
    __shared__ float hv[512];
    __shared__ float red[16][65];
    __shared__ int   sidx[16];

    int blk = blockIdx.x;
    int b = blk >> 3, l0 = (blk & 7) * 16;
    int t = threadIdx.x;

    if (mode == 0) { hv[t] = hfw[b*256 + t]; hv[256 + t] = hbw[b*256 + t]; }
    if (mode == 2 && t < 16) sidx[t] = g_idx[b*LL + l0 + t];

    int li = t >> 4, mj = t & 15;
    int srow = t >> 6, sk = t & 63;
    float cacc[4] = {0.f, 0.f, 0.f, 0.f};
    float acc[4]  = {0.f, 0.f, 0.f, 0.f};
    __syncthreads();

    for (int c = 0; c < 8; c++) {
        #pragma unroll
        for (int i = 0; i < 16; i++) {
            int f = i * 256 + t; int m = f >> 6, k = f & 63;
            Kc[m][k] = Kmat[(size_t)m * D + c*64 + k];
        }
        #pragma unroll
        for (int i = 0; i < 4; i++) {
            int row = i*4 + srow;
            int gl = b*LL + l0 + row;
            float lv = Lr[(size_t)gl * D + c*64 + sk];
            float av;
            if (mode == 0)      av = hv[c*64 + sk];
            else if (mode == 1) av = g_att[(size_t)gl * D + c*64 + sk];
            else                av = Rr[(size_t)(b*LR + sidx[row]) * D + c*64 + sk];
            float p = lv * av;
            P[row][sk] = p;
            cacc[i] += p;
        }
        __syncthreads();
        #pragma unroll
        for (int k4 = 0; k4 < 16; k4++) {
            float4 p4 = *(const float4*)&P[li][k4*4];
            #pragma unroll
            for (int j = 0; j < 4; j++) {
                float4 kv = *(const float4*)&Kc[j*16 + mj][k4*4];
                acc[j] = fmaf(p4.x, kv.x, fmaf(p4.y, kv.y, fmaf(p4.z, kv.z, fmaf(p4.w, kv.w, acc[j]))));
            }
        }
        __syncthreads();
    }
    #pragma unroll
    for (int i = 0; i < 4; i++) red[i*4 + srow][sk] = cacc[i];
    __syncthreads();
    if (t < 16) {
        float s = 0.f;
        #pragma unroll
        for (int k = 0; k < 64; k++) s += red[t][k];
        out[(size_t)(b*LL + l0 + t) * OC + col0] = tanhf(s);
    }
    #pragma unroll
    for (int j = 0; j < 4; j++)
        out[(size_t)(b*LL + l0 + li) * OC + col0 + 1 + j*16 + mj] = tanhf(acc[j]);
}

// ============================================================================
extern "C" void kernel_launch(void* const* d_in, const int* in_sizes, int n_in,
                              void* d_out, int out_size)
{
    const float* reps_lt = (const float*)d_in[0];
    const float* reps_rt = (const float*)d_in[3];
    const float* h_rt_fw = (const float*)d_in[4];
    const float* h_rt_bw = (const float*)d_in[5];
    const float* k_full  = (const float*)d_in[6];
    const float* k_mpW   = (const float*)d_in[7];
    const float* attn_w1 = (const float*)d_in[8];
    const float* diag_w  = (const float*)d_in[9];
    const float* k_attW  = (const float*)d_in[10];
    const float* k_maxW  = (const float*)d_in[11];
    float* out = (float*)d_out;

    static cudaStream_t s2 = 0, s3 = 0;
    static cudaEvent_t  eF = 0, eJ2 = 0, eJ3 = 0;
    if (!s2) {
        cudaFuncSetAttribute(k_mpool_mma, cudaFuncAttributeMaxDynamicSharedMemorySize, 51200);
        cudaFuncSetAttribute(k_algt_mma,  cudaFuncAttributeMaxDynamicSharedMemorySize, 131072);
        cudaFuncSetAttribute(k_pr_mma,    cudaFuncAttributeMaxDynamicSharedMemorySize, 131072);
        cudaStreamCreateWithFlags(&s2, cudaStreamNonBlocking);
        cudaStreamCreateWithFlags(&s3, cudaStreamNonBlocking);
        cudaEventCreateWithFlags(&eF,  cudaEventDisableTiming);
        cudaEventCreateWithFlags(&eJ2, cudaEventDisableTiming);
        cudaEventCreateWithFlags(&eJ3, cudaEventDisableTiming);
    }

    // main: split L first (needed by mpool AND algt_mma), then fork
    k_split<<<dim3(8, B), 256>>>(reps_lt, 0);
    cudaEventRecord(eF, 0);
    cudaStreamWaitEvent(s2, eF, 0);
    cudaStreamWaitEvent(s3, eF, 0);

    // main stream: dominant tensor-core chain (cols 65..128)
    k_mpool_mma<<<dim3(64, B), 256, 51200>>>(reps_rt, k_mpW, out);

    // s2: attentive path -> mp3 mode1 (cols 129..193)
    k_splitRT<<<dim3(8, B), 256, 0, s2>>>(reps_rt);
    k_split<<<dim3(8, B), 256, 0, s2>>>(reps_rt, 1);
    k_splitW<<<dim3(8, 8), 256, 0, s2>>>(attn_w1);
    k_algt_mma<<<64, 256, 131072, s2>>>(diag_w);
    k_score<<<dim3(4, B), 256, 0, s2>>>();
    k_pr_mma<<<dim3(4, B), 256, 131072, s2>>>();
    k_mp3<<<256, 256, 0, s2>>>(reps_lt, h_rt_fw, h_rt_bw, k_attW, reps_rt, out, 1, 129);

    // s3: full match (cols 0..64) + max-attentive -> mp3 mode2 (cols 194..258)
    k_mp3<<<256, 256, 0, s3>>>(reps_lt, h_rt_fw, h_rt_bw, k_full, reps_rt, out, 0, 0);
    k_nrt<<<512, 256, 0, s3>>>(reps_rt);
    k_idx<<<dim3(4, B), 256, 0, s3>>>(reps_lt, reps_rt);
    k_mp3<<<256, 256, 0, s3>>>(reps_lt, h_rt_fw, h_rt_bw, k_maxW, reps_rt, out, 2, 194);

    // join side streams back into the main stream
    cudaEventRecord(eJ2, s2);
    cudaEventRecord(eJ3, s3);
    cudaStreamWaitEvent(0, eJ2, 0);
    cudaStreamWaitEvent(0, eJ3, 0);
}

// round 16
// speedup vs baseline: 1.9982x; 1.1011x over previous
#include <cuda_runtime.h>
#include <math.h>
#include <stdint.h>

#define B   32
#define LL  128
#define LR  128
#define D   512
#define A   128
#define OC  259   // 1+64 | 64 | 1+64 | 1+64

// ---- scratch (static device globals; no runtime allocation) ----
__device__ float g_algt[(B*LL + B*LR) * A];
__device__ float g_att[B*LL*D];
__device__ float g_invnrt[B*LR];
__device__ int   g_idx[B*LL];
// pre-split bf16 hi/lo swizzled tiles: (b,chunk) tiles of 128 rows x 128B
__device__ __align__(16) unsigned char g_Lh[B*8*16384];
__device__ __align__(16) unsigned char g_Ll[B*8*16384];
__device__ __align__(16) unsigned char g_Lf[B*8*16384];   // fp16 single (mpool A)
__device__ __align__(16) unsigned char g_Rh[B*8*16384];
__device__ __align__(16) unsigned char g_Rl[B*8*16384];
__device__ __align__(16) unsigned char g_Rf[B*8*16384];   // fp16 single (mpool B src)
// W1 transposed to B-operand tiles: 8 chunks x (128 a-rows x 64 d) hi/lo
__device__ __align__(16) unsigned char g_Wh[8*16384];
__device__ __align__(16) unsigned char g_Wl[8*16384];
// softmax probs as A-operand tiles: (b, r-chunk) of 128 l-rows x 64 r
__device__ __align__(16) unsigned char g_Ph[B*2*16384];
__device__ __align__(16) unsigned char g_Pl[B*2*16384];
// R transposed to B-operand tiles: (b, nt*2+rc): 128 d-rows x 64 r
__device__ __align__(16) unsigned char g_RTh[B*8*16384];
__device__ __align__(16) unsigned char g_RTl[B*8*16384];

__device__ __forceinline__ uint32_t swz(uint32_t x){ return x ^ ((x >> 3) & 0x70u); }
__device__ __forceinline__ uint32_t smem_u32(const void* p){
    uint32_t a;
    asm("{ .reg .u64 t; cvta.to.shared.u64 t, %1; cvt.u32.u64 %0, t; }" : "=r"(a) : "l"(p));
    return a;
}
__device__ __forceinline__ void split2(float x0, float x1, uint32_t& h, uint32_t& l){
    asm("cvt.rn.bf16x2.f32 %0, %1, %2;" : "=r"(h) : "f"(x1), "f"(x0));
    float h0 = __uint_as_float(h << 16), h1 = __uint_as_float(h & 0xffff0000u);
    asm("cvt.rn.bf16x2.f32 %0, %1, %2;" : "=r"(l) : "f"(x1 - h1), "f"(x0 - h0));
}
__device__ __forceinline__ uint32_t pack_f16(float x0, float x1){
    uint32_t h;
    asm("cvt.rn.f16x2.f32 %0, %1, %2;" : "=r"(h) : "f"(x1), "f"(x0));
    return h;
}
__device__ __forceinline__ uint32_t hmul2(uint32_t a, uint32_t b){
    uint32_t d;
    asm("mul.f16x2 %0, %1, %2;" : "=r"(d) : "r"(a), "r"(b));
    return d;
}

#define LDSM4(r0,r1,r2,r3,addr) \
    asm volatile("ldmatrix.sync.aligned.m8n8.x4.shared.b16 {%0,%1,%2,%3}, [%4];" \
        : "=r"(r0),"=r"(r1),"=r"(r2),"=r"(r3) : "r"(addr))
#define CP16(s,g) \
    asm volatile("cp.async.cg.shared.global [%0], [%1], 16;" :: "r"(s), "l"(g))
#define CPCOMMIT() asm volatile("cp.async.commit_group;")
#define CPWAIT1()  asm volatile("cp.async.wait_group 1;")
#define CPWAIT0()  asm volatile("cp.async.wait_group 0;")

__device__ __forceinline__ void mma_bf16(float* d, const uint32_t* a, const uint32_t* b){
    asm volatile("mma.sync.aligned.m16n8k16.row.col.f32.bf16.bf16.f32 "
        "{%0,%1,%2,%3}, {%4,%5,%6,%7}, {%8,%9}, {%0,%1,%2,%3};"
        : "+f"(d[0]),"+f"(d[1]),"+f"(d[2]),"+f"(d[3])
        : "r"(a[0]),"r"(a[1]),"r"(a[2]),"r"(a[3]), "r"(b[0]),"r"(b[1]));
}
__device__ __forceinline__ void mma_f16(float* d, const uint32_t* a, const uint32_t* b){
    asm volatile("mma.sync.aligned.m16n8k16.row.col.f32.f16.f16.f32 "
        "{%0,%1,%2,%3}, {%4,%5,%6,%7}, {%8,%9}, {%0,%1,%2,%3};"
        : "+f"(d[0]),"+f"(d[1]),"+f"(d[2]),"+f"(d[3])
        : "r"(a[0]),"r"(a[1]),"r"(a[2]),"r"(a[3]), "r"(b[0]),"r"(b[1]));
}

// ============================================================================
// k_split: X (fp32) -> bf16 hi/lo tiles + fp16 tile. grid (8, B). 0=L 1=R
// ============================================================================
__global__ void __launch_bounds__(256) k_split(const float* __restrict__ X, int which)
{
    int c = blockIdx.x, b = blockIdx.y, t = threadIdx.x;
    const float* Xb = X + ((size_t)b << 16) + c*64;
    size_t tile = ((size_t)(b*8 + c)) << 14;
    unsigned char* dh = (which ? g_Rh : g_Lh) + tile;
    unsigned char* dl = (which ? g_Rl : g_Ll) + tile;
    unsigned char* df = (which ? g_Rf : g_Lf) + tile;
    #pragma unroll
    for (int i = 0; i < 4; i++){
        int f = i*256 + t; int row = f >> 3, q = f & 7;
        const float* src = Xb + (size_t)row*512 + q*8;
        float4 v0 = *(const float4*)src, v1 = *(const float4*)(src + 4);
        uint32_t h01,l01,h23,l23,h45,l45,h67,l67;
        split2(v0.x, v0.y, h01, l01);
        split2(v0.z, v0.w, h23, l23);
        split2(v1.x, v1.y, h45, l45);
        split2(v1.z, v1.w, h67, l67);
        uint32_t off = swz((uint32_t)(row*128 + q*16));
        *(uint4*)(dh + off) = make_uint4(h01, h23, h45, h67);
        *(uint4*)(dl + off) = make_uint4(l01, l23, l45, l67);
        uint4 fp;
        fp.x = pack_f16(v0.x, v0.y); fp.y = pack_f16(v0.z, v0.w);
        fp.z = pack_f16(v1.x, v1.y); fp.w = pack_f16(v1.z, v1.w);
        *(uint4*)(df + off) = fp;
    }
}

// ============================================================================
// k_splitW: W1 [d=512][a=128] -> transposed B tiles. grid (8, 8).
// ============================================================================
__global__ void __launch_bounds__(256) k_splitW(const float* __restrict__ W1)
{
    int c = blockIdx.x, t = threadIdx.x;
    size_t tile = ((size_t)c) << 14;
    int i = blockIdx.y;
    {
        int f = i*256 + t; int row = f >> 4, q = f & 15;
        int d0 = c*64 + q*4;
        float w0 = W1[(size_t)(d0+0)*A + row];
        float w1 = W1[(size_t)(d0+1)*A + row];
        float w2 = W1[(size_t)(d0+2)*A + row];
        float w3 = W1[(size_t)(d0+3)*A + row];
        uint32_t h01,l01,h23,l23;
        split2(w0, w1, h01, l01);
        split2(w2, w3, h23, l23);
        uint32_t off = swz((uint32_t)(row*128 + q*8));
        *(uint2*)(g_Wh + tile + off) = make_uint2(h01, h23);
        *(uint2*)(g_Wl + tile + off) = make_uint2(l01, l23);
    }
}

// ============================================================================
// k_splitRT: R -> transposed B tiles (rows=d, k=r). grid (8, B); j = nt*2+rc.
// ============================================================================
__global__ void __launch_bounds__(256) k_splitRT(const float* __restrict__ Rr)
{
    __shared__ __align__(16) float Rsm[64*132];
    int j = blockIdx.x, b = blockIdx.y, t = threadIdx.x;
    int nt = j >> 1, rc = j & 1;
    const float* src = Rr + ((size_t)b << 16) + (size_t)(rc*64)*512 + nt*128;
    #pragma unroll
    for (int i = 0; i < 8; i++){
        int f = i*256 + t; int row = f >> 5, dc = (f & 31)*4;
        *(float4*)&Rsm[row*132 + dc] = *(const float4*)(src + (size_t)row*512 + dc);
    }
    __syncthreads();
    size_t tile = ((size_t)(b*8 + j)) << 14;
    #pragma unroll
    for (int i = 0; i < 4; i++){
        int f = i*256 + t; int drow = f >> 3, oct = f & 7;
        int r0 = oct*8;
        float v[8];
        #pragma unroll
        for (int k = 0; k < 8; k++) v[k] = Rsm[(r0+k)*132 + drow];
        uint32_t h01,l01,h23,l23,h45,l45,h67,l67;
        split2(v[0],v[1],h01,l01); split2(v[2],v[3],h23,l23);
        split2(v[4],v[5],h45,l45); split2(v[6],v[7],h67,l67);
        uint32_t off = swz((uint32_t)(drow*128 + oct*16));
        *(uint4*)(g_RTh + tile + off) = make_uint4(h01,h23,h45,h67);
        *(uint4*)(g_RTl + tile + off) = make_uint4(l01,l23,l45,l67);
    }
}

// ============================================================================
// k_mpool_mma: CTA = (m, b).  C[l,r] = sum_d L[l,d]*(R[r,d]*K_m[d]).
// Single-term fp16.  A = L fp16 tiles (cp.async dbl-buffered);
// B = g_Rf tile scaled by packed-fp16 K via mul.f16x2 (1 LDG + 4 HMUL2 + 1 STS
// per 8 elements).  out[b,l,65+m] = tanh(max_r C).
// dyn smem: A[2] 32K | Bf 16K | sKp 1K = 50176 B, occ 2.
// ============================================================================
__global__ void __launch_bounds__(256, 2) k_mpool_mma(
    const float* __restrict__ Kmp, float* __restrict__ out)
{
    extern __shared__ __align__(16) unsigned char dyn[];
    int m = blockIdx.x, b = blockIdx.y;
    int t = threadIdx.x, wid = t >> 5, lane = t & 31;
    uint32_t base = smem_u32(dyn);
    uint32_t Abuf[2] = {base, base + 16384};
    uint32_t Bf = base + 32768;
    uint32_t* sKp = (uint32_t*)(dyn + 49152);
    {   // pack K_m to fp16 pairs: sKp[c*32 + q] = (K[c*64+2q], K[c*64+2q+1])
        const float* kp = Kmp + (size_t)m*512 + t*2;
        sKp[t] = pack_f16(kp[0], kp[1]);
    }

    {
        const unsigned char* gf = g_Lf + (((size_t)(b*8)) << 14);
        #pragma unroll
        for (int i = 0; i < 4; i++){
            uint32_t o = (uint32_t)(i*256 + t) * 16;
            CP16(Abuf[0] + o, gf + o);
        }
        CPCOMMIT();
    }
    __syncthreads();

    int wl = wid >> 2, wn = wid & 3;
    float acc[4][4][4];
    #pragma unroll
    for (int i = 0; i < 4; i++)
        #pragma unroll
        for (int j = 0; j < 4; j++)
            #pragma unroll
            for (int k = 0; k < 4; k++) acc[i][j][k] = 0.f;

    int rowA = lane & 15;
    int cbA  = lane >> 4;
    int rowB = ((lane >> 4) & 1) * 8 + (lane & 7);
    int cbB  = (lane >> 3) & 1;

    int rrow = t >> 3, rq = t & 7;

    for (int c = 0; c < 8; c++){
        if (c < 7){
            uint32_t nb = Abuf[(c+1) & 1];
            const unsigned char* gf = g_Lf + (((size_t)(b*8 + c+1)) << 14);
            #pragma unroll
            for (int i = 0; i < 4; i++){
                uint32_t o = (uint32_t)(i*256 + t) * 16;
                CP16(nb + o, gf + o);
            }
            CPCOMMIT();
        }
        // build B = fp16(R)*fp16(K_m): tile layout matches, pure packed mul
        {
            const unsigned char* rf = g_Rf + (((size_t)(b*8 + c)) << 14);
            uint32_t kp0 = sKp[c*32 + rq*4 + 0];
            uint32_t kp1 = sKp[c*32 + rq*4 + 1];
            uint32_t kp2 = sKp[c*32 + rq*4 + 2];
            uint32_t kp3 = sKp[c*32 + rq*4 + 3];
            #pragma unroll
            for (int i = 0; i < 4; i++){
                int row = rrow + i*32;
                uint32_t off = swz((uint32_t)(row*128 + rq*16));
                uint4 rv = *(const uint4*)(rf + off);
                uint32_t p0 = hmul2(rv.x, kp0);
                uint32_t p1 = hmul2(rv.y, kp1);
                uint32_t p2 = hmul2(rv.z, kp2);
                uint32_t p3 = hmul2(rv.w, kp3);
                asm volatile("st.shared.v4.b32 [%0], {%1,%2,%3,%4};"
                             :: "r"(Bf+off), "r"(p0), "r"(p1), "r"(p2), "r"(p3));
            }
        }
        if (c < 7) { CPWAIT1(); } else { CPWAIT0(); }
        __syncthreads();

        uint32_t Af = Abuf[c & 1];
        #pragma unroll
        for (int ks = 0; ks < 4; ks++){
            uint32_t aoffs[4], boffs[2];
            #pragma unroll
            for (int mt = 0; mt < 4; mt++)
                aoffs[mt] = swz((uint32_t)((wl*64 + mt*16 + rowA)*128 + ks*32 + cbA*16));
            #pragma unroll
            for (int jp = 0; jp < 2; jp++)
                boffs[jp] = swz((uint32_t)((wn*32 + jp*16 + rowB)*128 + ks*32 + cbB*16));

            uint32_t bf_[4][2];
            #pragma unroll
            for (int jp = 0; jp < 2; jp++)
                LDSM4(bf_[jp*2][0], bf_[jp*2][1], bf_[jp*2+1][0], bf_[jp*2+1][1], Bf + boffs[jp]);
            uint32_t af_[4][4];
            #pragma unroll
            for (int mt = 0; mt < 4; mt++)
                LDSM4(af_[mt][0], af_[mt][1], af_[mt][2], af_[mt][3], Af + aoffs[mt]);
            #pragma unroll
            for (int mt = 0; mt < 4; mt++)
                #pragma unroll
                for (int nt = 0; nt < 4; nt++)
                    mma_f16(acc[mt][nt], af_[mt], bf_[nt]);
        }
        __syncthreads();
    }

    float* red = (float*)dyn;
    int g = lane >> 2, tg = lane & 3;
    #pragma unroll
    for (int mt = 0; mt < 4; mt++){
        float m0 = -1e30f, m1 = -1e30f;
        #pragma unroll
        for (int nt = 0; nt < 4; nt++){
            m0 = fmaxf(m0, fmaxf(acc[mt][nt][0], acc[mt][nt][1]));
            m1 = fmaxf(m1, fmaxf(acc[mt][nt][2], acc[mt][nt][3]));
        }
        m0 = fmaxf(m0, __shfl_xor_sync(0xffffffffu, m0, 1));
        m0 = fmaxf(m0, __shfl_xor_sync(0xffffffffu, m0, 2));
        m1 = fmaxf(m1, __shfl_xor_sync(0xffffffffu, m1, 1));
        m1 = fmaxf(m1, __shfl_xor_sync(0xffffffffu, m1, 2));
        if (tg == 0){
            red[(wl*64 + mt*16 + g)*4 + wn]     = m0;
            red[(wl*64 + mt*16 + g + 8)*4 + wn] = m1;
        }
    }
    __syncthreads();
    if (t < 128){
        float v = fmaxf(fmaxf(red[t*4], red[t*4+1]), fmaxf(red[t*4+2], red[t*4+3]));
        out[((size_t)(b*LL + t))*OC + 65 + m] = tanhf(v);
    }
}

// ============================================================================
// k_algt_mma: tanh([L;R] @ W1) (*diag for L rows).  grid 64, dbl-buf 131072 B.
// ============================================================================
__global__ void __launch_bounds__(256) k_algt_mma(const float* __restrict__ diag)
{
    extern __shared__ __align__(16) unsigned char dyn[];
    __shared__ float sdiag[128];
    int bi = blockIdx.x;
    int isL = (bi < 32) ? 1 : 0;
    int b = isL ? bi : bi - 32;
    int t = threadIdx.x, wid = t >> 5, lane = t & 31;
    uint32_t base = smem_u32(dyn);
    uint32_t buf[2] = {base, base + 65536};

    if (t < 128) sdiag[t] = diag[t];

    const unsigned char* srcH = isL ? g_Lh : g_Rh;
    const unsigned char* srcL = isL ? g_Ll : g_Rl;

    {
        const unsigned char* ah = srcH + (((size_t)(b*8)) << 14);
        const unsigned char* al = srcL + (((size_t)(b*8)) << 14);
        #pragma unroll
        for (int i = 0; i < 4; i++){
            uint32_t o = (uint32_t)(i*256 + t) * 16;
            CP16(buf[0] + o,         ah + o);
            CP16(buf[0] + 16384 + o, al + o);
            CP16(buf[0] + 32768 + o, g_Wh + o);
            CP16(buf[0] + 49152 + o, g_Wl + o);
        }
        CPCOMMIT();
    }

    int wl = wid >> 2, wn = wid & 3;
    float acc[4][4][4];
    #pragma unroll
    for (int i = 0; i < 4; i++)
        #pragma unroll
        for (int j = 0; j < 4; j++)
            #pragma unroll
            for (int k = 0; k < 4; k++) acc[i][j][k] = 0.f;

    int rowA = lane & 15;
    int cbA  = lane >> 4;
    int rowB = ((lane >> 4) & 1) * 8 + (lane & 7);
    int cbB  = (lane >> 3) & 1;

    for (int c = 0; c < 8; c++){
        if (c < 7){
            uint32_t nb = buf[(c+1) & 1];
            const unsigned char* ah = srcH + (((size_t)(b*8 + c+1)) << 14);
            const unsigned char* al = srcL + (((size_t)(b*8 + c+1)) << 14);
            const unsigned char* wh = g_Wh + (((size_t)(c+1)) << 14);
            const unsigned char* wlp = g_Wl + (((size_t)(c+1)) << 14);
            #pragma unroll
            for (int i = 0; i < 4; i++){
                uint32_t o = (uint32_t)(i*256 + t) * 16;
                CP16(nb + o,         ah + o);
                CP16(nb + 16384 + o, al + o);
                CP16(nb + 32768 + o, wh + o);
                CP16(nb + 49152 + o, wlp + o);
            }
            CPCOMMIT();
        }
        if (c < 7) { CPWAIT1(); } else { CPWAIT0(); }
        __syncthreads();

        uint32_t Ah = buf[c & 1], Al = Ah + 16384, Wh = Ah + 32768, Wlb = Ah + 49152;
        #pragma unroll
        for (int ks = 0; ks < 4; ks++){
            uint32_t aoffs[4], boffs[2];
            #pragma unroll
            for (int mt = 0; mt < 4; mt++)
                aoffs[mt] = swz((uint32_t)((wl*64 + mt*16 + rowA)*128 + ks*32 + cbA*16));
            #pragma unroll
            for (int jp = 0; jp < 2; jp++)
                boffs[jp] = swz((uint32_t)((wn*32 + jp*16 + rowB)*128 + ks*32 + cbB*16));

            uint32_t bh_[4][2];
            #pragma unroll
            for (int jp = 0; jp < 2; jp++)
                LDSM4(bh_[jp*2][0], bh_[jp*2][1], bh_[jp*2+1][0], bh_[jp*2+1][1], Wh + boffs[jp]);
            {
                uint32_t al_[4][4];
                #pragma unroll
                for (int mt = 0; mt < 4; mt++)
                    LDSM4(al_[mt][0], al_[mt][1], al_[mt][2], al_[mt][3], Al + aoffs[mt]);
                #pragma unroll
                for (int mt = 0; mt < 4; mt++)
                    #pragma unroll
                    for (int nt = 0; nt < 4; nt++)
                        mma_bf16(acc[mt][nt], al_[mt], bh_[nt]);
            }
            uint32_t ah_[4][4];
            #pragma unroll
            for (int mt = 0; mt < 4; mt++)
                LDSM4(ah_[mt][0], ah_[mt][1], ah_[mt][2], ah_[mt][3], Ah + aoffs[mt]);
            #pragma unroll
            for (int mt = 0; mt < 4; mt++)
                #pragma unroll
                for (int nt = 0; nt < 4; nt++)
                    mma_bf16(acc[mt][nt], ah_[mt], bh_[nt]);
            {
                uint32_t bl_[4][2];
                #pragma unroll
                for (int jp = 0; jp < 2; jp++)
                    LDSM4(bl_[jp*2][0], bl_[jp*2][1], bl_[jp*2+1][0], bl_[jp*2+1][1], Wlb + boffs[jp]);
                #pragma unroll
                for (int mt = 0; mt < 4; mt++)
                    #pragma unroll
                    for (int nt = 0; nt < 4; nt++)
                        mma_bf16(acc[mt][nt], ah_[mt], bl_[nt]);
            }
        }
        __syncthreads();
    }

    int g = lane >> 2, tg = lane & 3;
    size_t rbase = (size_t)bi * 128;
    #pragma unroll
    for (int mt = 0; mt < 4; mt++){
        int r0 = wl*64 + mt*16 + g, r1 = r0 + 8;
        #pragma unroll
        for (int nt = 0; nt < 4; nt++){
            int col = wn*32 + nt*8 + tg*2;
            float d0 = isL ? sdiag[col] : 1.f;
            float d1 = isL ? sdiag[col+1] : 1.f;
            float2 v0 = make_float2(tanhf(acc[mt][nt][0])*d0, tanhf(acc[mt][nt][1])*d1);
            float2 v1 = make_float2(tanhf(acc[mt][nt][2])*d0, tanhf(acc[mt][nt][3])*d1);
            *(float2*)&g_algt[(rbase + r0)*A + col] = v0;
            *(float2*)&g_algt[(rbase + r1)*A + col] = v1;
        }
    }
}

// ============================================================================
// k_score: register-tiled scores + softmax -> bf16 hi/lo P-tiles.
// grid (4, B): 32 l x 128 r.
// ============================================================================
__global__ void __launch_bounds__(256) k_score()
{
    __shared__ float Ls[16*36];
    __shared__ float Rs[16*132];
    __shared__ __align__(16) float S[32*132];

    int b = blockIdx.y, l0 = blockIdx.x*32, t = threadIdx.x;
    int ly = t >> 4, tx = t & 15;
    float acc[2][8];
    #pragma unroll
    for (int i = 0; i < 2; i++)
        #pragma unroll
        for (int j = 0; j < 8; j++) acc[i][j] = 0.f;

    const float* Lb = g_algt + (size_t)(b*LL + l0) * A;
    const float* Rb = g_algt + (size_t)(B*LL + b*LR) * A;

    for (int kc = 0; kc < 8; kc++){
        __syncthreads();
        {
            int row = t >> 3, c2 = (t & 7)*2;
            float2 v = *(const float2*)(Lb + (size_t)row*A + kc*16 + c2);
            Ls[c2*36 + row] = v.x;
            Ls[(c2+1)*36 + row] = v.y;
        }
        {
            int row = t >> 1, c8 = (t & 1)*8;
            const float* src = Rb + (size_t)row*A + kc*16 + c8;
            float4 v0 = *(const float4*)src, v1 = *(const float4*)(src + 4);
            Rs[(c8+0)*132 + row] = v0.x; Rs[(c8+1)*132 + row] = v0.y;
            Rs[(c8+2)*132 + row] = v0.z; Rs[(c8+3)*132 + row] = v0.w;
            Rs[(c8+4)*132 + row] = v1.x; Rs[(c8+5)*132 + row] = v1.y;
            Rs[(c8+6)*132 + row] = v1.z; Rs[(c8+7)*132 + row] = v1.w;
        }
        __syncthreads();
        #pragma unroll
        for (int k = 0; k < 16; k++){
            float a0 = Ls[k*36 + ly], a1 = Ls[k*36 + ly + 16];
            float4 b0 = *(const float4*)&Rs[k*132 + tx*8];
            float4 b1 = *(const float4*)&Rs[k*132 + tx*8 + 4];
            float bv[8] = {b0.x,b0.y,b0.z,b0.w,b1.x,b1.y,b1.z,b1.w};
            #pragma unroll
            for (int j = 0; j < 8; j++){
                acc[0][j] = fmaf(a0, bv[j], acc[0][j]);
                acc[1][j] = fmaf(a1, bv[j], acc[1][j]);
            }
        }
    }
    #pragma unroll
    for (int i = 0; i < 2; i++)
        #pragma unroll
        for (int j = 0; j < 8; j++)
            S[(ly + i*16)*132 + tx*8 + j] = acc[i][j];
    __syncthreads();

    int w = t >> 5, lane = t & 31;
    #pragma unroll
    for (int rr = w*4; rr < w*4 + 4; rr++){
        float v0 = S[rr*132+lane], v1 = S[rr*132+lane+32],
              v2 = S[rr*132+lane+64], v3 = S[rr*132+lane+96];
        float m0 = fmaxf(fmaxf(v0,v1), fmaxf(v2,v3));
        #pragma unroll
        for (int off = 16; off; off >>= 1) m0 = fmaxf(m0, __shfl_xor_sync(0xffffffffu, m0, off));
        float e0 = expf(v0-m0), e1 = expf(v1-m0), e2 = expf(v2-m0), e3 = expf(v3-m0);
        float sum = e0+e1+e2+e3;
        #pragma unroll
        for (int off = 16; off; off >>= 1) sum += __shfl_xor_sync(0xffffffffu, sum, off);
        float inv = 1.f / sum;
        S[rr*132+lane] = e0*inv; S[rr*132+lane+32] = e1*inv;
        S[rr*132+lane+64] = e2*inv; S[rr*132+lane+96] = e3*inv;
    }
    __syncthreads();

    #pragma unroll
    for (int it = 0; it < 2; it++){
        int f = it*256 + t;
        int row = f >> 4, oct = f & 15;
        int c = oct >> 3;
        const float* sp = &S[row*132 + oct*8];
        float4 p0 = *(const float4*)sp, p1 = *(const float4*)(sp + 4);
        uint32_t h01,l01,h23,l23,h45,l45,h67,l67;
        split2(p0.x,p0.y,h01,l01); split2(p0.z,p0.w,h23,l23);
        split2(p1.x,p1.y,h45,l45); split2(p1.z,p1.w,h67,l67);
        int l = l0 + row;
        uint32_t off = swz((uint32_t)(l*128 + (oct & 7)*16));
        size_t tile = ((size_t)(b*2 + c)) << 14;
        *(uint4*)(g_Ph + tile + off) = make_uint4(h01,h23,h45,h67);
        *(uint4*)(g_Pl + tile + off) = make_uint4(l01,l23,l45,l67);
    }
}

// ============================================================================
// k_pr_mma: att = P @ R via 3-term split bf16 MMA.  grid (4 d-tiles, B).
// ============================================================================
__global__ void __launch_bounds__(256) k_pr_mma()
{
    extern __shared__ __align__(16) unsigned char dyn[];
    int nt = blockIdx.x, b = blockIdx.y;
    int t = threadIdx.x, wid = t >> 5, lane = t & 31;
    uint32_t base = smem_u32(dyn);

    {
        const unsigned char* ph = g_Ph + (((size_t)(b*2)) << 14);
        const unsigned char* pl = g_Pl + (((size_t)(b*2)) << 14);
        const unsigned char* bh = g_RTh + (((size_t)(b*8 + nt*2)) << 14);
        const unsigned char* bl = g_RTl + (((size_t)(b*8 + nt*2)) << 14);
        #pragma unroll
        for (int i = 0; i < 8; i++){
            uint32_t o = (uint32_t)(i*256 + t) * 16;
            CP16(base + o,          ph + o);
            CP16(base + 32768 + o,  pl + o);
            CP16(base + 65536 + o,  bh + o);
            CP16(base + 98304 + o,  bl + o);
        }
        CPCOMMIT(); CPWAIT0();
    }
    __syncthreads();

    int wl = wid >> 2, wn = wid & 3;
    float acc[4][4][4];
    #pragma unroll
    for (int i = 0; i < 4; i++)
        #pragma unroll
        for (int j = 0; j < 4; j++)
            #pragma unroll
            for (int k = 0; k < 4; k++) acc[i][j][k] = 0.f;

    int rowA = lane & 15;
    int cbA  = lane >> 4;
    int rowB = ((lane >> 4) & 1) * 8 + (lane & 7);
    int cbB  = (lane >> 3) & 1;

    for (int ks8 = 0; ks8 < 8; ks8++){
        int ch = ks8 >> 2, ks = ks8 & 3;
        uint32_t Ah = base + ch*16384,         Al  = base + 32768 + ch*16384;
        uint32_t Bh = base + 65536 + ch*16384, Blb = base + 98304 + ch*16384;
        uint32_t aoffs[4], boffs[2];
        #pragma unroll
        for (int mt = 0; mt < 4; mt++)
            aoffs[mt] = swz((uint32_t)((wl*64 + mt*16 + rowA)*128 + ks*32 + cbA*16));
        #pragma unroll
        for (int jp = 0; jp < 2; jp++)
            boffs[jp] = swz((uint32_t)((wn*32 + jp*16 + rowB)*128 + ks*32 + cbB*16));

        uint32_t bh_[4][2];
        #pragma unroll
        for (int jp = 0; jp < 2; jp++)
            LDSM4(bh_[jp*2][0], bh_[jp*2][1], bh_[jp*2+1][0], bh_[jp*2+1][1], Bh + boffs[jp]);
        {
            uint32_t al_[4][4];
            #pragma unroll
            for (int mt = 0; mt < 4; mt++)
                LDSM4(al_[mt][0], al_[mt][1], al_[mt][2], al_[mt][3], Al + aoffs[mt]);
            #pragma unroll
            for (int mt = 0; mt < 4; mt++)
                #pragma unroll
                for (int n2 = 0; n2 < 4; n2++)
                    mma_bf16(acc[mt][n2], al_[mt], bh_[n2]);
        }
        uint32_t ah_[4][4];
        #pragma unroll
        for (int mt = 0; mt < 4; mt++)
            LDSM4(ah_[mt][0], ah_[mt][1], ah_[mt][2], ah_[mt][3], Ah + aoffs[mt]);
        #pragma unroll
        for (int mt = 0; mt < 4; mt++)
            #pragma unroll
            for (int n2 = 0; n2 < 4; n2++)
                mma_bf16(acc[mt][n2], ah_[mt], bh_[n2]);
        {
            uint32_t bl_[4][2];
            #pragma unroll
            for (int jp = 0; jp < 2; jp++)
                LDSM4(bl_[jp*2][0], bl_[jp*2][1], bl_[jp*2+1][0], bl_[jp*2+1][1], Blb + boffs[jp]);
            #pragma unroll
            for (int mt = 0; mt < 4; mt++)
                #pragma unroll
                for (int n2 = 0; n2 < 4; n2++)
                    mma_bf16(acc[mt][n2], ah_[mt], bl_[n2]);
        }
    }

    int g = lane >> 2, tg = lane & 3;
    float* ob = g_att + ((size_t)(b*LL))*D + nt*128;
    #pragma unroll
    for (int mt = 0; mt < 4; mt++){
        int r0 = wl*64 + mt*16 + g, r1 = r0 + 8;
        #pragma unroll
        for (int n2 = 0; n2 < 4; n2++){
            int col = wn*32 + n2*8 + tg*2;
            *(float2*)&ob[(size_t)r0*D + col] = make_float2(acc[mt][n2][0], acc[mt][n2][1]);
            *(float2*)&ob[(size_t)r1*D + col] = make_float2(acc[mt][n2][2], acc[mt][n2][3]);
        }
    }
}

// ============================================================================
// k_nrt: inv right norms, grid 512 (one warp per row)
// ============================================================================
__global__ void k_nrt(const float* __restrict__ Rr)
{
    int blk = blockIdx.x;
    int b = blk >> 4, r = (blk & 15)*8 + (threadIdx.x >> 5);
    int lane = threadIdx.x & 31;
    const float* row = Rr + (size_t)(b*LR + r) * D;
    float s = 0.f;
    #pragma unroll 4
    for (int i = lane; i < D; i += 32){ float v = row[i]; s = fmaf(v, v, s); }
    #pragma unroll
    for (int off = 16; off; off >>= 1) s += __shfl_xor_sync(0xffffffffu, s, off);
    if (!lane) g_invnrt[b*LR + r] = rsqrtf(fmaxf(s, 1e-6f));
}

// ============================================================================
// k_idx: argmax_r cosine(L[l], R[r]).  block = 32 l x 128 r, grid (4, B).
// ============================================================================
__global__ void __launch_bounds__(256) k_idx(
    const float* __restrict__ Lr, const float* __restrict__ Rr)
{
    __shared__ float Ls[16*36];
    __shared__ float Rs[16*132];
    __shared__ float sn[128];
    __shared__ float redv[32*17];
    __shared__ int   redi[32*17];

    int b = blockIdx.y, l0 = blockIdx.x*32, t = threadIdx.x;
    if (t < 128) sn[t] = g_invnrt[b*LR + t];

    int ly = t >> 4, tx = t & 15;
    float acc[2][8];
    #pragma unroll
    for (int i = 0; i < 2; i++)
        #pragma unroll
        for (int j = 0; j < 8; j++) acc[i][j] = 0.f;

    const float* Lb = Lr + (size_t)(b*LL + l0) * D;
    const float* Rb = Rr + ((size_t)b << 16);

    for (int kc = 0; kc < 32; kc++){
        __syncthreads();
        {
            int row = t >> 3, c2 = (t & 7)*2;
            float2 v = *(const float2*)(Lb + (size_t)row*D + kc*16 + c2);
            Ls[c2*36 + row] = v.x;
            Ls[(c2+1)*36 + row] = v.y;
        }
        {
            int row = t >> 1, c8 = (t & 1)*8;
            const float* src = Rb + (size_t)row*D + kc*16 + c8;
            float4 v0 = *(const float4*)src, v1 = *(const float4*)(src + 4);
            Rs[(c8+0)*132 + row] = v0.x; Rs[(c8+1)*132 + row] = v0.y;
            Rs[(c8+2)*132 + row] = v0.z; Rs[(c8+3)*132 + row] = v0.w;
            Rs[(c8+4)*132 + row] = v1.x; Rs[(c8+5)*132 + row] = v1.y;
            Rs[(c8+6)*132 + row] = v1.z; Rs[(c8+7)*132 + row] = v1.w;
        }
        __syncthreads();
        #pragma unroll
        for (int k = 0; k < 16; k++){
            float a0 = Ls[k*36 + ly], a1 = Ls[k*36 + ly + 16];
            float4 b0 = *(const float4*)&Rs[k*132 + tx*8];
            float4 b1 = *(const float4*)&Rs[k*132 + tx*8 + 4];
            float bv[8] = {b0.x,b0.y,b0.z,b0.w,b1.x,b1.y,b1.z,b1.w};
            #pragma unroll
            for (int j = 0; j < 8; j++){
                acc[0][j] = fmaf(a0, bv[j], acc[0][j]);
                acc[1][j] = fmaf(a1, bv[j], acc[1][j]);
            }
        }
    }
    #pragma unroll
    for (int i = 0; i < 2; i++){
        float bv = -1e30f; int bi = 0;
        #pragma unroll
        for (int j = 0; j < 8; j++){
            float v = acc[i][j] * sn[tx*8 + j];
            if (v > bv){ bv = v; bi = tx*8 + j; }
        }
        redv[(ly + i*16)*17 + tx] = bv;
        redi[(ly + i*16)*17 + tx] = bi;
    }
    __syncthreads();
    if (t < 32){
        float bv = -1e30f; int bi = 0;
        #pragma unroll
        for (int j = 0; j < 16; j++){
            float v = redv[t*17 + j];
            if (v > bv){ bv = v; bi = redi[t*17 + j]; }
        }
        g_idx[b*LL + l0 + t] = bi;
    }
}

// ============================================================================
// k_mp3: one mp_match epilogue (mode per launch).  grid 256.
// ============================================================================
__global__ void __launch_bounds__(256) k_mp3(
    const float* __restrict__ Lr, const float* __restrict__ hfw,
    const float* __restrict__ hbw, const float* __restrict__ Kmat,
    const float* __restrict__ Rr, float* __restrict__ out,
    int mode, int col0)
{
    __shared__ __align__(16) float P[16][68];
    __shared__ __align__(16) float Kc[64][68];
    __shared__ float hv[512];
    __shared__ float red[16][65];
    __shared__ int   sidx[16];

    int blk = blockIdx.x;
    int b = blk >> 3, l0 = (blk & 7) * 16;
    int t = threadIdx.x;

    if (mode == 0) { hv[t] = hfw[b*256 + t]; hv[256 + t] = hbw[b*256 + t]; }
    if (mode == 2 && t < 16) sidx[t] = g_idx[b*LL + l0 + t];

    int li = t >> 4, mj = t & 15;
    int srow = t >> 6, sk = t & 63;
    float cacc[4] = {0.f, 0.f, 0.f, 0.f};
    float acc[4]  = {0.f, 0.f, 0.f, 0.f};
    __syncthreads();

    for (int c = 0; c < 8; c++) {
        #pragma unroll
        for (int i = 0; i < 16; i++) {
            int f = i * 256 + t; int m = f >> 6, k = f & 63;
            Kc[m][k] = Kmat[(size_t)m * D + c*64 + k];
        }
        #pragma unroll
        for (int i = 0; i < 4; i++) {
            int row = i*4 + srow;
            int gl = b*LL + l0 + row;
            float lv = Lr[(size_t)gl * D + c*64 + sk];
            float av;
            if (mode == 0)      av = hv[c*64 + sk];
            else if (mode == 1) av = g_att[(size_t)gl * D + c*64 + sk];
            else                av = Rr[(size_t)(b*LR + sidx[row]) * D + c*64 + sk];
            float p = lv * av;
            P[row][sk] = p;
            cacc[i] += p;
        }
        __syncthreads();
        #pragma unroll
        for (int k4 = 0; k4 < 16; k4++) {
            float4 p4 = *(const float4*)&P[li][k4*4];
            #pragma unroll
            for (int j = 0; j < 4; j++) {
                float4 kv = *(const float4*)&Kc[j*16 + mj][k4*4];
                acc[j] = fmaf(p4.x, kv.x, fmaf(p4.y, kv.y, fmaf(p4.z, kv.z, fmaf(p4.w, kv.w, acc[j]))));
            }
        }
        __syncthreads();
    }
    #pragma unroll
    for (int i = 0; i < 4; i++) red[i*4 + srow][sk] = cacc[i];
    __syncthreads();
    if (t < 16) {
        float s = 0.f;
        #pragma unroll
        for (int k = 0; k < 64; k++) s += red[t][k];
        out[(size_t)(b*LL + l0 + t) * OC + col0] = tanhf(s);
    }
    #pragma unroll
    for (int j = 0; j < 4; j++)
        out[(size_t)(b*LL + l0 + li) * OC + col0 + 1 + j*16 + mj] = tanhf(acc[j]);
}

// ============================================================================
extern "C" void kernel_launch(void* const* d_in, const int* in_sizes, int n_in,
                              void* d_out, int out_size)
{
    const float* reps_lt = (const float*)d_in[0];
    const float* reps_rt = (const float*)d_in[3];
    const float* h_rt_fw = (const float*)d_in[4];
    const float* h_rt_bw = (const float*)d_in[5];
    const float* k_full  = (const float*)d_in[6];
    const float* k_mpW   = (const float*)d_in[7];
    const float* attn_w1 = (const float*)d_in[8];
    const float* diag_w  = (const float*)d_in[9];
    const float* k_attW  = (const float*)d_in[10];
    const float* k_maxW  = (const float*)d_in[11];
    float* out = (float*)d_out;

    static cudaStream_t s2 = 0, s3 = 0;
    static cudaEvent_t  eF = 0, eJ2 = 0, eJ3 = 0;
    if (!s2) {
        cudaFuncSetAttribute(k_mpool_mma, cudaFuncAttributeMaxDynamicSharedMemorySize, 50176);
        cudaFuncSetAttribute(k_algt_mma,  cudaFuncAttributeMaxDynamicSharedMemorySize, 131072);
        cudaFuncSetAttribute(k_pr_mma,    cudaFuncAttributeMaxDynamicSharedMemorySize, 131072);
        cudaStreamCreateWithFlags(&s2, cudaStreamNonBlocking);
        cudaStreamCreateWithFlags(&s3, cudaStreamNonBlocking);
        cudaEventCreateWithFlags(&eF,  cudaEventDisableTiming);
        cudaEventCreateWithFlags(&eJ2, cudaEventDisableTiming);
        cudaEventCreateWithFlags(&eJ3, cudaEventDisableTiming);
    }

    // main: split L and R (mpool consumes g_Lf + g_Rf), then fork
    k_split<<<dim3(8, B), 256>>>(reps_lt, 0);
    k_split<<<dim3(8, B), 256>>>(reps_rt, 1);
    cudaEventRecord(eF, 0);
    cudaStreamWaitEvent(s2, eF, 0);
    cudaStreamWaitEvent(s3, eF, 0);

    // main stream: dominant tensor-core chain (cols 65..128)
    k_mpool_mma<<<dim3(64, B), 256, 50176>>>(k_mpW, out);

    // s2: attentive path -> mp3 mode1 (cols 129..193)
    k_splitRT<<<dim3(8, B), 256, 0, s2>>>(reps_rt);
    k_splitW<<<dim3(8, 8), 256, 0, s2>>>(attn_w1);
    k_algt_mma<<<64, 256, 131072, s2>>>(diag_w);
    k_score<<<dim3(4, B), 256, 0, s2>>>();
    k_pr_mma<<<dim3(4, B), 256, 131072, s2>>>();
    k_mp3<<<256, 256, 0, s2>>>(reps_lt, h_rt_fw, h_rt_bw, k_attW, reps_rt, out, 1, 129);

    // s3: full match (cols 0..64) + max-attentive -> mp3 mode2 (cols 194..258)
    k_mp3<<<256, 256, 0, s3>>>(reps_lt, h_rt_fw, h_rt_bw, k_full, reps_rt, out, 0, 0);
    k_nrt<<<512, 256, 0, s3>>>(reps_rt);
    k_idx<<<dim3(4, B), 256, 0, s3>>>(reps_lt, reps_rt);
    k_mp3<<<256, 256, 0, s3>>>(reps_lt, h_rt_fw, h_rt_bw, k_maxW, reps_rt, out, 2, 194);

    // join side streams back into the main stream
    cudaEventRecord(eJ2, s2);
    cudaEventRecord(eJ3, s3);
    cudaStreamWaitEvent(0, eJ2, 0);
    cudaStreamWaitEvent(0, eJ3, 0);
}